// round 3
// baseline (speedup 1.0000x reference)
#include <cuda_runtime.h>

// Problem constants
#define BATCH   2
#define TSEQ    2048
#define NHEAD   16
#define DHEAD   64
#define DMODEL  1024
#define BH      (BATCH * NHEAD)        // 32
#define MROWS   (BATCH * TSEQ)         // 4096
#define N_QKV   (3 * NHEAD * DHEAD)    // 3072
#define ATTN_SCALE 0.125f              // 1/sqrt(64)
#define LN_EPS  1e-5f

// ---------------- scratch (static device globals; no allocations) ----------
__device__ float g_q [BH * TSEQ * DHEAD];   // [bh][t][d]
__device__ float g_k [BH * TSEQ * DHEAD];
__device__ float g_v [BH * TSEQ * DHEAD];
__device__ float g_av[BH * TSEQ * DHEAD];   // attention out, flat L = b*16+h
__device__ float g_y [MROWS * DMODEL];      // residual + attn_out (pre-LN)

// ===========================================================================
// Kernel 1: QKV GEMM.  out[m][n] = sum_k inp[m][k] * Wqkv[n][k] + b[n]
// 128x128x8 tile, 256 threads, 8x8 per thread. Epilogue scatters into
// g_q/g_k/g_v with layout [b*16+h][t][d].
// ===========================================================================
__global__ __launch_bounds__(256) void qkv_gemm_kernel(
    const float* __restrict__ A,      // [4096][1024]
    const float* __restrict__ W,      // [3072][1024]
    const float* __restrict__ bias)   // [3072]
{
    __shared__ __align__(16) float As[8][132];
    __shared__ __align__(16) float Bs[8][132];

    const int tid   = threadIdx.x;
    const int mBase = blockIdx.y * 128;
    const int nBase = blockIdx.x * 128;
    const int tr = (tid >> 4) * 8;     // 0..120
    const int tc = (tid & 15) * 8;

    const int lr = tid >> 1;           // 0..127
    const int lk = (tid & 1) * 4;      // 0 or 4

    const float* Ap = A + (size_t)(mBase + lr) * DMODEL + lk;
    const float* Wp = W + (size_t)(nBase + lr) * DMODEL + lk;

    float acc[8][8];
#pragma unroll
    for (int i = 0; i < 8; i++)
#pragma unroll
        for (int j = 0; j < 8; j++) acc[i][j] = 0.f;

    for (int k0 = 0; k0 < DMODEL; k0 += 8) {
        float4 av = *(const float4*)(Ap + k0);
        float4 bv = *(const float4*)(Wp + k0);
        As[lk + 0][lr] = av.x; As[lk + 1][lr] = av.y;
        As[lk + 2][lr] = av.z; As[lk + 3][lr] = av.w;
        Bs[lk + 0][lr] = bv.x; Bs[lk + 1][lr] = bv.y;
        Bs[lk + 2][lr] = bv.z; Bs[lk + 3][lr] = bv.w;
        __syncthreads();
#pragma unroll
        for (int k = 0; k < 8; k++) {
            float4 a0 = *(const float4*)&As[k][tr];
            float4 a1 = *(const float4*)&As[k][tr + 4];
            float4 b0 = *(const float4*)&Bs[k][tc];
            float4 b1 = *(const float4*)&Bs[k][tc + 4];
            float a[8] = {a0.x, a0.y, a0.z, a0.w, a1.x, a1.y, a1.z, a1.w};
            float b[8] = {b0.x, b0.y, b0.z, b0.w, b1.x, b1.y, b1.z, b1.w};
#pragma unroll
            for (int i = 0; i < 8; i++)
#pragma unroll
                for (int j = 0; j < 8; j++) acc[i][j] += a[i] * b[j];
        }
        __syncthreads();
    }

    // epilogue: add bias, scatter into Q/K/V [bh][t][d]
#pragma unroll
    for (int i = 0; i < 8; i++) {
        int m  = mBase + tr + i;
        int bb = m >> 11;          // batch
        int t  = m & 2047;
#pragma unroll
        for (int j4 = 0; j4 < 8; j4 += 4) {
            int n     = nBase + tc + j4;
            int third = n >> 10;
            int nn    = n & 1023;
            int h     = nn >> 6;
            int d     = nn & 63;
            float4 bi = *(const float4*)(bias + n);
            float4 o;
            o.x = acc[i][j4 + 0] + bi.x;
            o.y = acc[i][j4 + 1] + bi.y;
            o.z = acc[i][j4 + 2] + bi.z;
            o.w = acc[i][j4 + 3] + bi.w;
            float* base = (third == 0) ? g_q : ((third == 1) ? g_k : g_v);
            *(float4*)(base + ((bb * NHEAD + h) * TSEQ + t) * DHEAD + d) = o;
        }
    }
}

// ===========================================================================
// Kernel 2: streaming (flash-style) attention. One CTA per (bh, q-tile of 64).
// 256 threads = 16x16, each owns 4x4 of a 64x64 tile.
// ===========================================================================
#define ST 68                                       // padded smem row stride
#define ATTN_SMEM_FLOATS (4 * 64 * ST + 3 * 64)
#define ATTN_SMEM_BYTES  (ATTN_SMEM_FLOATS * 4)     // 70400 B

__global__ __launch_bounds__(256) void attn_kernel()
{
    extern __shared__ __align__(16) float sm[];
    float* Qs   = sm;                 // [d][m] transposed, stride ST
    float* Ks   = sm + 64 * ST;       // [d][n] transposed
    float* Vs   = sm + 2 * 64 * ST;   // [n][d] natural
    float* Ss   = sm + 3 * 64 * ST;   // [m][n] scores / probs
    float* rowm = sm + 4 * 64 * ST;   // [64] running max
    float* rowl = rowm + 64;          // [64] running denom
    float* rowc = rowl + 64;          // [64] correction factor

    const int tid = threadIdx.x;
    const int bh  = blockIdx.y;
    const int q0  = blockIdx.x * 64;
    const int ry  = (tid >> 4) * 4;   // 4 query rows
    const int cx  = (tid & 15) * 4;   // 4 key cols / 4 d cols

    float oacc[4][4];
#pragma unroll
    for (int i = 0; i < 4; i++)
#pragma unroll
        for (int j = 0; j < 4; j++) oacc[i][j] = 0.f;

    if (tid < 64) { rowm[tid] = -1e30f; rowl[tid] = 0.f; }

    // load Q tile transposed
    {
        const float* gq = g_q + (bh * TSEQ + q0) * DHEAD;
#pragma unroll
        for (int pass = 0; pass < 4; pass++) {
            int m = pass * 16 + (tid >> 4);
            int d = (tid & 15) * 4;
            float4 v = *(const float4*)(gq + m * DHEAD + d);
            Qs[(d + 0) * ST + m] = v.x;
            Qs[(d + 1) * ST + m] = v.y;
            Qs[(d + 2) * ST + m] = v.z;
            Qs[(d + 3) * ST + m] = v.w;
        }
    }

    for (int kt = 0; kt < TSEQ / 64; kt++) {
        __syncthreads();   // prior GEMM2 done reading Vs/Ss; Q visible on iter0
        const float* gk = g_k + (bh * TSEQ + kt * 64) * DHEAD;
        const float* gv = g_v + (bh * TSEQ + kt * 64) * DHEAD;
#pragma unroll
        for (int pass = 0; pass < 4; pass++) {
            int m = pass * 16 + (tid >> 4);
            int d = (tid & 15) * 4;
            float4 kv = *(const float4*)(gk + m * DHEAD + d);
            Ks[(d + 0) * ST + m] = kv.x;
            Ks[(d + 1) * ST + m] = kv.y;
            Ks[(d + 2) * ST + m] = kv.z;
            Ks[(d + 3) * ST + m] = kv.w;
            float4 vv = *(const float4*)(gv + m * DHEAD + d);
            *(float4*)&Vs[m * ST + d] = vv;
        }
        __syncthreads();

        // ---- GEMM1: S = Q @ K^T ----
        float s[4][4];
#pragma unroll
        for (int i = 0; i < 4; i++)
#pragma unroll
            for (int j = 0; j < 4; j++) s[i][j] = 0.f;
#pragma unroll 16
        for (int k = 0; k < 64; k++) {
            float4 a = *(const float4*)&Qs[k * ST + ry];
            float4 b = *(const float4*)&Ks[k * ST + cx];
            s[0][0] += a.x * b.x; s[0][1] += a.x * b.y; s[0][2] += a.x * b.z; s[0][3] += a.x * b.w;
            s[1][0] += a.y * b.x; s[1][1] += a.y * b.y; s[1][2] += a.y * b.z; s[1][3] += a.y * b.w;
            s[2][0] += a.z * b.x; s[2][1] += a.z * b.y; s[2][2] += a.z * b.z; s[2][3] += a.z * b.w;
            s[3][0] += a.w * b.x; s[3][1] += a.w * b.y; s[3][2] += a.w * b.z; s[3][3] += a.w * b.w;
        }
#pragma unroll
        for (int i = 0; i < 4; i++) {
            float4 o;
            o.x = s[i][0] * ATTN_SCALE;
            o.y = s[i][1] * ATTN_SCALE;
            o.z = s[i][2] * ATTN_SCALE;
            o.w = s[i][3] * ATTN_SCALE;
            *(float4*)&Ss[(ry + i) * ST + cx] = o;
        }
        __syncthreads();

        // ---- online softmax: one thread per row ----
        if (tid < 64) {
            float mprev = rowm[tid];
            float mx    = mprev;
            float* srow = &Ss[tid * ST];
#pragma unroll 16
            for (int c = 0; c < 64; c++) mx = fmaxf(mx, srow[c]);
            float corr = __expf(mprev - mx);
            float sum  = 0.f;
#pragma unroll 16
            for (int c = 0; c < 64; c++) {
                float p = __expf(srow[c] - mx);
                srow[c] = p;
                sum += p;
            }
            rowl[tid] = rowl[tid] * corr + sum;
            rowm[tid] = mx;
            rowc[tid] = corr;
        }
        __syncthreads();

        // ---- GEMM2: O = O*corr + P @ V ----
        float c0 = rowc[ry + 0], c1 = rowc[ry + 1], c2 = rowc[ry + 2], c3 = rowc[ry + 3];
#pragma unroll
        for (int j = 0; j < 4; j++) {
            oacc[0][j] *= c0; oacc[1][j] *= c1; oacc[2][j] *= c2; oacc[3][j] *= c3;
        }
#pragma unroll 16
        for (int k = 0; k < 64; k++) {
            float4 bv = *(const float4*)&Vs[k * ST + cx];
            float a0 = Ss[(ry + 0) * ST + k];
            float a1 = Ss[(ry + 1) * ST + k];
            float a2 = Ss[(ry + 2) * ST + k];
            float a3 = Ss[(ry + 3) * ST + k];
            oacc[0][0] += a0 * bv.x; oacc[0][1] += a0 * bv.y; oacc[0][2] += a0 * bv.z; oacc[0][3] += a0 * bv.w;
            oacc[1][0] += a1 * bv.x; oacc[1][1] += a1 * bv.y; oacc[1][2] += a1 * bv.z; oacc[1][3] += a1 * bv.w;
            oacc[2][0] += a2 * bv.x; oacc[2][1] += a2 * bv.y; oacc[2][2] += a2 * bv.z; oacc[2][3] += a2 * bv.w;
            oacc[3][0] += a3 * bv.x; oacc[3][1] += a3 * bv.y; oacc[3][2] += a3 * bv.z; oacc[3][3] += a3 * bv.w;
        }
    }

    // writeback normalized output
    float* go = g_av + (bh * TSEQ + q0) * DHEAD;
#pragma unroll
    for (int i = 0; i < 4; i++) {
        int r = ry + i;
        float inv = 1.0f / rowl[r];
        float4 o;
        o.x = oacc[i][0] * inv;
        o.y = oacc[i][1] * inv;
        o.z = oacc[i][2] * inv;
        o.w = oacc[i][3] * inv;
        *(float4*)(go + r * DHEAD + cx) = o;
    }
}

// ===========================================================================
// Kernel 3: O projection + residual.
// y[m][n] = sum_c av_perm[m][c] * Wo[n][c] + inp[m][n]
// where av_perm[(b2,t)][h2*64+d] = g_av[h2*2 + b2][t][d]   (reference's
// (H,B)-view reassembly quirk).
// ===========================================================================
__global__ __launch_bounds__(256) void oproj_kernel(
    const float* __restrict__ inp,    // [4096][1024]
    const float* __restrict__ Wo)     // [1024][1024]
{
    __shared__ __align__(16) float As[8][132];
    __shared__ __align__(16) float Bs[8][132];

    const int tid   = threadIdx.x;
    const int mBase = blockIdx.y * 128;
    const int nBase = blockIdx.x * 128;
    const int tr = (tid >> 4) * 8;
    const int tc = (tid & 15) * 8;

    const int lr = tid >> 1;
    const int lk = (tid & 1) * 4;

    const int m  = mBase + lr;
    const int b2 = m >> 11;
    const int t  = m & 2047;
    const float* Wp = Wo + (size_t)(nBase + lr) * DMODEL + lk;

    float acc[8][8];
#pragma unroll
    for (int i = 0; i < 8; i++)
#pragma unroll
        for (int j = 0; j < 8; j++) acc[i][j] = 0.f;

    for (int k0 = 0; k0 < DMODEL; k0 += 8) {
        int c  = k0 + lk;
        int h2 = c >> 6;
        int d  = c & 63;
        float4 av = *(const float4*)(g_av + ((h2 * BATCH + b2) * TSEQ + t) * DHEAD + d);
        float4 bv = *(const float4*)(Wp + k0);
        As[lk + 0][lr] = av.x; As[lk + 1][lr] = av.y;
        As[lk + 2][lr] = av.z; As[lk + 3][lr] = av.w;
        Bs[lk + 0][lr] = bv.x; Bs[lk + 1][lr] = bv.y;
        Bs[lk + 2][lr] = bv.z; Bs[lk + 3][lr] = bv.w;
        __syncthreads();
#pragma unroll
        for (int k = 0; k < 8; k++) {
            float4 a0 = *(const float4*)&As[k][tr];
            float4 a1 = *(const float4*)&As[k][tr + 4];
            float4 b0 = *(const float4*)&Bs[k][tc];
            float4 b1 = *(const float4*)&Bs[k][tc + 4];
            float a[8] = {a0.x, a0.y, a0.z, a0.w, a1.x, a1.y, a1.z, a1.w};
            float b[8] = {b0.x, b0.y, b0.z, b0.w, b1.x, b1.y, b1.z, b1.w};
#pragma unroll
            for (int i = 0; i < 8; i++)
#pragma unroll
                for (int j = 0; j < 8; j++) acc[i][j] += a[i] * b[j];
        }
        __syncthreads();
    }

    // epilogue: residual add, write g_y
#pragma unroll
    for (int i = 0; i < 8; i++) {
        int mm = mBase + tr + i;
#pragma unroll
        for (int j4 = 0; j4 < 8; j4 += 4) {
            int n = nBase + tc + j4;
            float4 r = *(const float4*)(inp + (size_t)mm * DMODEL + n);
            float4 o;
            o.x = acc[i][j4 + 0] + r.x;
            o.y = acc[i][j4 + 1] + r.y;
            o.z = acc[i][j4 + 2] + r.z;
            o.w = acc[i][j4 + 3] + r.w;
            *(float4*)(g_y + (size_t)mm * DMODEL + n) = o;
        }
    }
}

// ===========================================================================
// Kernel 4: LayerNorm. One warp per row of 1024.
// ===========================================================================
__global__ __launch_bounds__(256) void ln_kernel(
    const float* __restrict__ gamma,
    const float* __restrict__ beta,
    float* __restrict__ out)
{
    const int row  = blockIdx.x * 8 + (threadIdx.x >> 5);
    const int lane = threadIdx.x & 31;
    const float* x = g_y + (size_t)row * DMODEL;

    float4 v[8];
    float s1 = 0.f, s2 = 0.f;
#pragma unroll
    for (int i = 0; i < 8; i++) {
        v[i] = *(const float4*)(x + lane * 4 + i * 128);
        s1 += v[i].x + v[i].y + v[i].z + v[i].w;
        s2 += v[i].x * v[i].x + v[i].y * v[i].y + v[i].z * v[i].z + v[i].w * v[i].w;
    }
#pragma unroll
    for (int off = 16; off > 0; off >>= 1) {
        s1 += __shfl_xor_sync(0xFFFFFFFFu, s1, off);
        s2 += __shfl_xor_sync(0xFFFFFFFFu, s2, off);
    }
    float mu   = s1 * (1.0f / DMODEL);
    float var  = s2 * (1.0f / DMODEL) - mu * mu;
    float rstd = rsqrtf(var + LN_EPS);

    float* o = out + (size_t)row * DMODEL;
#pragma unroll
    for (int i = 0; i < 8; i++) {
        int cbase = lane * 4 + i * 128;
        float4 g = *(const float4*)(gamma + cbase);
        float4 b = *(const float4*)(beta + cbase);
        float4 r;
        r.x = (v[i].x - mu) * rstd * g.x + b.x;
        r.y = (v[i].y - mu) * rstd * g.y + b.y;
        r.z = (v[i].z - mu) * rstd * g.z + b.z;
        r.w = (v[i].w - mu) * rstd * g.w + b.w;
        *(float4*)(o + cbase) = r;
    }
}

// ===========================================================================
extern "C" void kernel_launch(void* const* d_in, const int* in_sizes, int n_in,
                              void* d_out, int out_size)
{
    const float* inp   = (const float*)d_in[0];
    const float* Wqkv  = (const float*)d_in[1];
    const float* bqkv  = (const float*)d_in[2];
    const float* Wo    = (const float*)d_in[3];
    const float* gamma = (const float*)d_in[4];
    const float* beta  = (const float*)d_in[5];
    float* out = (float*)d_out;

    cudaFuncSetAttribute(attn_kernel,
                         cudaFuncAttributeMaxDynamicSharedMemorySize,
                         ATTN_SMEM_BYTES);

    qkv_gemm_kernel<<<dim3(N_QKV / 128, MROWS / 128), 256>>>(inp, Wqkv, bqkv);
    attn_kernel<<<dim3(TSEQ / 64, BH), 256, ATTN_SMEM_BYTES>>>();
    oproj_kernel<<<dim3(DMODEL / 128, MROWS / 128), 256>>>(inp, Wo);
    ln_kernel<<<MROWS / 8, 256>>>(gamma, beta, out);
}

// round 4
// speedup vs baseline: 2.3021x; 2.3021x over previous
#include <cuda_runtime.h>
#include <cstdint>

// Problem constants
#define BATCH   2
#define TSEQ    2048
#define NHEAD   16
#define DHEAD   64
#define DMODEL  1024
#define BH      (BATCH * NHEAD)        // 32
#define MROWS   (BATCH * TSEQ)         // 4096
#define N_QKV   (3 * NHEAD * DHEAD)    // 3072
#define ATTN_SCALE 0.125f              // 1/sqrt(64)
#define LN_EPS  1e-5f

// ---------------- scratch (static device globals; no allocations) ----------
__device__ float g_q [BH * TSEQ * DHEAD];   // [bh][t][d]
__device__ float g_k [BH * TSEQ * DHEAD];
__device__ float g_v [BH * TSEQ * DHEAD];
__device__ float g_av[BH * TSEQ * DHEAD];   // attention out, flat L = b*16+h
__device__ float g_y [MROWS * DMODEL];      // residual + attn_out (pre-LN)

// ---------------- tf32 helpers --------------------------------------------
__device__ __forceinline__ float tf32r(float x) {
    uint32_t u;
    asm("cvt.rna.tf32.f32 %0, %1;" : "=r"(u) : "f"(x));
    return __uint_as_float(u);
}

// mma.sync m16n8k8 tf32: D = A*B + D.
// A frag: a0=(gid,tg) a1=(gid+8,tg) a2=(gid,tg+4) a3=(gid+8,tg+4)
// B frag: b0=(k=tg,n=gid) b1=(k=tg+4,n=gid)
// C frag: c0=(gid,2tg) c1=(gid,2tg+1) c2=(gid+8,2tg) c3=(gid+8,2tg+1)
__device__ __forceinline__ void mma_tf32(float* c, const uint32_t* a,
                                         uint32_t b0, uint32_t b1) {
    asm volatile(
        "mma.sync.aligned.m16n8k8.row.col.f32.tf32.tf32.f32 "
        "{%0,%1,%2,%3}, {%4,%5,%6,%7}, {%8,%9}, {%0,%1,%2,%3};"
        : "+f"(c[0]), "+f"(c[1]), "+f"(c[2]), "+f"(c[3])
        : "r"(a[0]), "r"(a[1]), "r"(a[2]), "r"(a[3]), "r"(b0), "r"(b1));
}

// ===========================================================================
// Kernel 1: QKV GEMM (tf32 mma).  out[m][n] = inp[m][:]·Wqkv[n][:] + b[n]
// Block 128x128, 256 thr (8 warps as 4(m)x2(n)); warp tile 32x64.
// Epilogue scatters into g_q/g_k/g_v with layout [b*16+h][t][d].
// ===========================================================================
#define GST 36   // smem row stride (36 % 32 == 4 -> conflict-free frag loads)

__global__ __launch_bounds__(256) void qkv_gemm_kernel(
    const float* __restrict__ A,      // [4096][1024]
    const float* __restrict__ W,      // [3072][1024]
    const float* __restrict__ bias)   // [3072]
{
    __shared__ __align__(16) float As[128][GST];
    __shared__ __align__(16) float Bs[128][GST];

    const int tid  = threadIdx.x;
    const int lane = tid & 31;
    const int warp = tid >> 5;
    const int gid  = lane >> 2;
    const int tg   = lane & 3;
    const int wm   = warp & 3;        // 0..3 -> m offset *32
    const int wn   = warp >> 2;       // 0..1 -> n offset *64
    const int mBase = blockIdx.y * 128;
    const int nBase = blockIdx.x * 128;

    const int lrow = tid >> 1;        // 0..127
    const int lcol = (tid & 1) * 16;  // 0 or 16

    const float* Ap = A + (size_t)(mBase + lrow) * DMODEL + lcol;
    const float* Wp = W + (size_t)(nBase + lrow) * DMODEL + lcol;

    float acc[2][8][4];
#pragma unroll
    for (int mi = 0; mi < 2; mi++)
#pragma unroll
        for (int ni = 0; ni < 8; ni++)
#pragma unroll
            for (int j = 0; j < 4; j++) acc[mi][ni][j] = 0.f;

    for (int k0 = 0; k0 < DMODEL; k0 += 32) {
#pragma unroll
        for (int i = 0; i < 4; i++) {
            float4 a = *(const float4*)(Ap + k0 + i * 4);
            float4 b = *(const float4*)(Wp + k0 + i * 4);
            float4 ar = make_float4(tf32r(a.x), tf32r(a.y), tf32r(a.z), tf32r(a.w));
            float4 br = make_float4(tf32r(b.x), tf32r(b.y), tf32r(b.z), tf32r(b.w));
            *(float4*)&As[lrow][lcol + i * 4] = ar;
            *(float4*)&Bs[lrow][lcol + i * 4] = br;
        }
        __syncthreads();
#pragma unroll
        for (int kk = 0; kk < 32; kk += 8) {
            uint32_t af[2][4];
#pragma unroll
            for (int mi = 0; mi < 2; mi++) {
                const float* qb = &As[wm * 32 + mi * 16 + gid][0];
                af[mi][0] = __float_as_uint(qb[kk + tg]);
                af[mi][1] = __float_as_uint(qb[8 * GST + kk + tg]);
                af[mi][2] = __float_as_uint(qb[kk + tg + 4]);
                af[mi][3] = __float_as_uint(qb[8 * GST + kk + tg + 4]);
            }
#pragma unroll
            for (int ni = 0; ni < 8; ni++) {
                const float* bb = &Bs[wn * 64 + ni * 8 + gid][0];
                uint32_t b0 = __float_as_uint(bb[kk + tg]);
                uint32_t b1 = __float_as_uint(bb[kk + tg + 4]);
                mma_tf32(acc[0][ni], af[0], b0, b1);
                mma_tf32(acc[1][ni], af[1], b0, b1);
            }
        }
        __syncthreads();
    }

    // epilogue: add bias, scatter into Q/K/V [bh][t][d]
#pragma unroll
    for (int mi = 0; mi < 2; mi++) {
        int r0 = mBase + wm * 32 + mi * 16 + gid;
        int r1 = r0 + 8;
        int bb0 = r0 >> 11, t0 = r0 & 2047;
        int bb1 = r1 >> 11, t1 = r1 & 2047;
#pragma unroll
        for (int ni = 0; ni < 8; ni++) {
            int n = nBase + wn * 64 + ni * 8 + tg * 2;
            int third = n >> 10;
            int nn = n & 1023;
            int h = nn >> 6, d = nn & 63;
            float* base = (third == 0) ? g_q : ((third == 1) ? g_k : g_v);
            float2 bi = *(const float2*)(bias + n);
            float2 lo = make_float2(acc[mi][ni][0] + bi.x, acc[mi][ni][1] + bi.y);
            float2 hi = make_float2(acc[mi][ni][2] + bi.x, acc[mi][ni][3] + bi.y);
            *(float2*)(base + ((bb0 * NHEAD + h) * TSEQ + t0) * DHEAD + d) = lo;
            *(float2*)(base + ((bb1 * NHEAD + h) * TSEQ + t1) * DHEAD + d) = hi;
        }
    }
}

// ===========================================================================
// Kernel 2: flash-style attention, tf32 mma.
// One CTA per (bh, 128-row q-block); 256 thr, 8 warps as 4(m)x2(n).
// ===========================================================================
#define AST 68   // 68 % 32 == 4 -> conflict-free frag loads
#define QS_OFF  0
#define KS_OFF  (128 * AST)                 // 8704
#define VS_OFF  (KS_OFF + 64 * AST)        // 13056  (V transposed: Vs[d][n])
#define PS_OFF  (VS_OFF + 64 * AST)        // 17408
#define RM_OFF  (PS_OFF + 128 * AST)       // 26112
#define RL_OFF  (RM_OFF + 128)
#define RC_OFF  (RL_OFF + 128)
#define ATTN_SMEM_FLOATS (RC_OFF + 128)    // 26496
#define ATTN_SMEM_BYTES  (ATTN_SMEM_FLOATS * 4)   // 105984

__global__ __launch_bounds__(256) void attn_kernel()
{
    extern __shared__ __align__(16) float sm[];
    float* rowm = sm + RM_OFF;
    float* rowl = sm + RL_OFF;
    float* rowc = sm + RC_OFF;

    const int tid  = threadIdx.x;
    const int lane = tid & 31;
    const int warp = tid >> 5;
    const int gid  = lane >> 2;
    const int tg   = lane & 3;
    const int wm   = warp & 3;       // row quarter (*32)
    const int wn   = warp >> 2;      // col half (*32)
    const int bh   = blockIdx.y;
    const int q0   = blockIdx.x * 128;

    float oacc[2][4][4];
#pragma unroll
    for (int mi = 0; mi < 2; mi++)
#pragma unroll
        for (int ni = 0; ni < 4; ni++)
#pragma unroll
            for (int j = 0; j < 4; j++) oacc[mi][ni][j] = 0.f;

    if (tid < 128) { rowm[tid] = -1e30f; rowl[tid] = 0.f; }

    // ---- load Q tile (tf32-rounded), natural [m][k] layout ----
    {
        const int qr = tid >> 1;
        const int cb = (tid & 1) * 32;
        const float* gq = g_q + (bh * TSEQ + q0 + qr) * DHEAD + cb;
#pragma unroll
        for (int i = 0; i < 8; i++) {
            float4 v = *(const float4*)(gq + i * 4);
            float4 r = make_float4(tf32r(v.x), tf32r(v.y), tf32r(v.z), tf32r(v.w));
            *(float4*)&sm[QS_OFF + qr * AST + cb + i * 4] = r;
        }
    }

    for (int kt = 0; kt < TSEQ / 64; kt++) {
        __syncthreads();   // prev GEMM2 done reading Ps/Vs; Q + stats visible

        // ---- fill K tile [n][k] ----
        {
            const int kr = tid >> 2;
            const int cb = (tid & 3) * 16;
            const float* gk = g_k + (bh * TSEQ + kt * 64 + kr) * DHEAD + cb;
#pragma unroll
            for (int i = 0; i < 4; i++) {
                float4 v = *(const float4*)(gk + i * 4);
                float4 r = make_float4(tf32r(v.x), tf32r(v.y), tf32r(v.z), tf32r(v.w));
                *(float4*)&sm[KS_OFF + kr * AST + cb + i * 4] = r;
            }
        }
        // ---- fill V transposed: Vs[d][n] ----
        {
            const int vn = tid & 63;
            const int db = (tid >> 6) * 16;
            const float* gv = g_v + (bh * TSEQ + kt * 64 + vn) * DHEAD + db;
#pragma unroll
            for (int i = 0; i < 4; i++) {
                float4 v = *(const float4*)(gv + i * 4);
                sm[VS_OFF + (db + i * 4 + 0) * AST + vn] = tf32r(v.x);
                sm[VS_OFF + (db + i * 4 + 1) * AST + vn] = tf32r(v.y);
                sm[VS_OFF + (db + i * 4 + 2) * AST + vn] = tf32r(v.z);
                sm[VS_OFF + (db + i * 4 + 3) * AST + vn] = tf32r(v.w);
            }
        }
        __syncthreads();

        // ---- GEMM1: S[128,64] = Q·K^T (warp tile 32x32) ----
        {
            float s[2][4][4];
#pragma unroll
            for (int mi = 0; mi < 2; mi++)
#pragma unroll
                for (int ni = 0; ni < 4; ni++)
#pragma unroll
                    for (int j = 0; j < 4; j++) s[mi][ni][j] = 0.f;
#pragma unroll
            for (int kk = 0; kk < 64; kk += 8) {
                uint32_t af[2][4];
#pragma unroll
                for (int mi = 0; mi < 2; mi++) {
                    const float* qb = &sm[QS_OFF + (wm * 32 + mi * 16 + gid) * AST];
                    af[mi][0] = __float_as_uint(qb[kk + tg]);
                    af[mi][1] = __float_as_uint(qb[8 * AST + kk + tg]);
                    af[mi][2] = __float_as_uint(qb[kk + tg + 4]);
                    af[mi][3] = __float_as_uint(qb[8 * AST + kk + tg + 4]);
                }
#pragma unroll
                for (int ni = 0; ni < 4; ni++) {
                    const float* kb = &sm[KS_OFF + (wn * 32 + ni * 8 + gid) * AST];
                    uint32_t b0 = __float_as_uint(kb[kk + tg]);
                    uint32_t b1 = __float_as_uint(kb[kk + tg + 4]);
                    mma_tf32(s[0][ni], af[0], b0, b1);
                    mma_tf32(s[1][ni], af[1], b0, b1);
                }
            }
            // store scaled scores (raw fp32) to Ps
#pragma unroll
            for (int mi = 0; mi < 2; mi++) {
                int r = wm * 32 + mi * 16 + gid;
#pragma unroll
                for (int ni = 0; ni < 4; ni++) {
                    int cc = wn * 32 + ni * 8 + tg * 2;
                    float2 lo = make_float2(s[mi][ni][0] * ATTN_SCALE, s[mi][ni][1] * ATTN_SCALE);
                    float2 hi = make_float2(s[mi][ni][2] * ATTN_SCALE, s[mi][ni][3] * ATTN_SCALE);
                    *(float2*)&sm[PS_OFF + r * AST + cc] = lo;
                    *(float2*)&sm[PS_OFF + (r + 8) * AST + cc] = hi;
                }
            }
        }
        __syncthreads();

        // ---- online softmax: 2 threads per row (32 cols each) ----
        {
            const int row = tid >> 1;
            const int cb  = (tid & 1) * 32;
            float* srow = &sm[PS_OFF + row * AST];
            float mprev = rowm[row];
            float mx = mprev;
#pragma unroll 8
            for (int c = 0; c < 32; c++) mx = fmaxf(mx, srow[cb + c]);
            mx = fmaxf(mx, __shfl_xor_sync(0xFFFFFFFFu, mx, 1));
            float corr = __expf(mprev - mx);
            float sum = 0.f;
#pragma unroll 8
            for (int c = 0; c < 32; c++) {
                float p = __expf(srow[cb + c] - mx);
                srow[cb + c] = tf32r(p);
                sum += p;
            }
            sum += __shfl_xor_sync(0xFFFFFFFFu, sum, 1);
            if ((tid & 1) == 0) {
                rowl[row] = rowl[row] * corr + sum;
                rowm[row] = mx;
                rowc[row] = corr;
            }
        }
        __syncthreads();

        // ---- GEMM2: O = O*corr + P·V (warp tile 32x32 over (m,d)) ----
#pragma unroll
        for (int mi = 0; mi < 2; mi++) {
            int r = wm * 32 + mi * 16 + gid;
            float cl = rowc[r], ch = rowc[r + 8];
#pragma unroll
            for (int ni = 0; ni < 4; ni++) {
                oacc[mi][ni][0] *= cl; oacc[mi][ni][1] *= cl;
                oacc[mi][ni][2] *= ch; oacc[mi][ni][3] *= ch;
            }
        }
#pragma unroll
        for (int kk = 0; kk < 64; kk += 8) {
            uint32_t af[2][4];
#pragma unroll
            for (int mi = 0; mi < 2; mi++) {
                const float* pb = &sm[PS_OFF + (wm * 32 + mi * 16 + gid) * AST];
                af[mi][0] = __float_as_uint(pb[kk + tg]);
                af[mi][1] = __float_as_uint(pb[8 * AST + kk + tg]);
                af[mi][2] = __float_as_uint(pb[kk + tg + 4]);
                af[mi][3] = __float_as_uint(pb[8 * AST + kk + tg + 4]);
            }
#pragma unroll
            for (int ni = 0; ni < 4; ni++) {
                const float* vb = &sm[VS_OFF + (wn * 32 + ni * 8 + gid) * AST];
                uint32_t b0 = __float_as_uint(vb[kk + tg]);
                uint32_t b1 = __float_as_uint(vb[kk + tg + 4]);
                mma_tf32(oacc[0][ni], af[0], b0, b1);
                mma_tf32(oacc[1][ni], af[1], b0, b1);
            }
        }
    }

    // ---- writeback normalized output ----
#pragma unroll
    for (int mi = 0; mi < 2; mi++) {
        int r = wm * 32 + mi * 16 + gid;
        float il = 1.0f / rowl[r];
        float ih = 1.0f / rowl[r + 8];
#pragma unroll
        for (int ni = 0; ni < 4; ni++) {
            int cc = wn * 32 + ni * 8 + tg * 2;
            float2 lo = make_float2(oacc[mi][ni][0] * il, oacc[mi][ni][1] * il);
            float2 hi = make_float2(oacc[mi][ni][2] * ih, oacc[mi][ni][3] * ih);
            *(float2*)(g_av + (bh * TSEQ + q0 + r) * DHEAD + cc) = lo;
            *(float2*)(g_av + (bh * TSEQ + q0 + r + 8) * DHEAD + cc) = hi;
        }
    }
}

// ===========================================================================
// Kernel 3: O projection + residual (tf32 mma).
// y[m][n] = sum_c av_perm[m][c]·Wo[n][c] + inp[m][n],
// av_perm[(b2,t)][h2*64+d] = g_av[h2*2+b2][t][d]  (reference (H,B)-view quirk)
// ===========================================================================
__global__ __launch_bounds__(256) void oproj_kernel(
    const float* __restrict__ inp,    // [4096][1024]
    const float* __restrict__ Wo)     // [1024][1024]
{
    __shared__ __align__(16) float As[128][GST];
    __shared__ __align__(16) float Bs[128][GST];

    const int tid  = threadIdx.x;
    const int lane = tid & 31;
    const int warp = tid >> 5;
    const int gid  = lane >> 2;
    const int tg   = lane & 3;
    const int wm   = warp & 3;
    const int wn   = warp >> 2;
    const int mBase = blockIdx.y * 128;
    const int nBase = blockIdx.x * 128;

    const int lrow = tid >> 1;
    const int lcol = (tid & 1) * 16;

    const int m  = mBase + lrow;
    const int b2 = m >> 11;
    const int t  = m & 2047;
    const float* Wp = Wo + (size_t)(nBase + lrow) * DMODEL + lcol;

    float acc[2][8][4];
#pragma unroll
    for (int mi = 0; mi < 2; mi++)
#pragma unroll
        for (int ni = 0; ni < 8; ni++)
#pragma unroll
            for (int j = 0; j < 4; j++) acc[mi][ni][j] = 0.f;

    for (int k0 = 0; k0 < DMODEL; k0 += 32) {
#pragma unroll
        for (int i = 0; i < 4; i++) {
            int c  = k0 + lcol + i * 4;
            int h2 = c >> 6;
            int d  = c & 63;
            float4 a = *(const float4*)(g_av + ((h2 * BATCH + b2) * TSEQ + t) * DHEAD + d);
            float4 b = *(const float4*)(Wp + k0 + i * 4);
            float4 ar = make_float4(tf32r(a.x), tf32r(a.y), tf32r(a.z), tf32r(a.w));
            float4 br = make_float4(tf32r(b.x), tf32r(b.y), tf32r(b.z), tf32r(b.w));
            *(float4*)&As[lrow][lcol + i * 4] = ar;
            *(float4*)&Bs[lrow][lcol + i * 4] = br;
        }
        __syncthreads();
#pragma unroll
        for (int kk = 0; kk < 32; kk += 8) {
            uint32_t af[2][4];
#pragma unroll
            for (int mi = 0; mi < 2; mi++) {
                const float* qb = &As[wm * 32 + mi * 16 + gid][0];
                af[mi][0] = __float_as_uint(qb[kk + tg]);
                af[mi][1] = __float_as_uint(qb[8 * GST + kk + tg]);
                af[mi][2] = __float_as_uint(qb[kk + tg + 4]);
                af[mi][3] = __float_as_uint(qb[8 * GST + kk + tg + 4]);
            }
#pragma unroll
            for (int ni = 0; ni < 8; ni++) {
                const float* bb = &Bs[wn * 64 + ni * 8 + gid][0];
                uint32_t b0 = __float_as_uint(bb[kk + tg]);
                uint32_t b1 = __float_as_uint(bb[kk + tg + 4]);
                mma_tf32(acc[0][ni], af[0], b0, b1);
                mma_tf32(acc[1][ni], af[1], b0, b1);
            }
        }
        __syncthreads();
    }

    // epilogue: residual add, write g_y
#pragma unroll
    for (int mi = 0; mi < 2; mi++) {
        int r0 = mBase + wm * 32 + mi * 16 + gid;
        int r1 = r0 + 8;
#pragma unroll
        for (int ni = 0; ni < 8; ni++) {
            int n = nBase + wn * 64 + ni * 8 + tg * 2;
            float2 i0 = *(const float2*)(inp + (size_t)r0 * DMODEL + n);
            float2 i1 = *(const float2*)(inp + (size_t)r1 * DMODEL + n);
            float2 lo = make_float2(acc[mi][ni][0] + i0.x, acc[mi][ni][1] + i0.y);
            float2 hi = make_float2(acc[mi][ni][2] + i1.x, acc[mi][ni][3] + i1.y);
            *(float2*)(g_y + (size_t)r0 * DMODEL + n) = lo;
            *(float2*)(g_y + (size_t)r1 * DMODEL + n) = hi;
        }
    }
}

// ===========================================================================
// Kernel 4: LayerNorm. One warp per row of 1024.
// ===========================================================================
__global__ __launch_bounds__(256) void ln_kernel(
    const float* __restrict__ gamma,
    const float* __restrict__ beta,
    float* __restrict__ out)
{
    const int row  = blockIdx.x * 8 + (threadIdx.x >> 5);
    const int lane = threadIdx.x & 31;
    const float* x = g_y + (size_t)row * DMODEL;

    float4 v[8];
    float s1 = 0.f, s2 = 0.f;
#pragma unroll
    for (int i = 0; i < 8; i++) {
        v[i] = *(const float4*)(x + lane * 4 + i * 128);
        s1 += v[i].x + v[i].y + v[i].z + v[i].w;
        s2 += v[i].x * v[i].x + v[i].y * v[i].y + v[i].z * v[i].z + v[i].w * v[i].w;
    }
#pragma unroll
    for (int off = 16; off > 0; off >>= 1) {
        s1 += __shfl_xor_sync(0xFFFFFFFFu, s1, off);
        s2 += __shfl_xor_sync(0xFFFFFFFFu, s2, off);
    }
    float mu   = s1 * (1.0f / DMODEL);
    float var  = s2 * (1.0f / DMODEL) - mu * mu;
    float rstd = rsqrtf(var + LN_EPS);

    float* o = out + (size_t)row * DMODEL;
#pragma unroll
    for (int i = 0; i < 8; i++) {
        int cbase = lane * 4 + i * 128;
        float4 g = *(const float4*)(gamma + cbase);
        float4 b = *(const float4*)(beta + cbase);
        float4 r;
        r.x = (v[i].x - mu) * rstd * g.x + b.x;
        r.y = (v[i].y - mu) * rstd * g.y + b.y;
        r.z = (v[i].z - mu) * rstd * g.z + b.z;
        r.w = (v[i].w - mu) * rstd * g.w + b.w;
        *(float4*)(o + cbase) = r;
    }
}

// ===========================================================================
extern "C" void kernel_launch(void* const* d_in, const int* in_sizes, int n_in,
                              void* d_out, int out_size)
{
    const float* inp   = (const float*)d_in[0];
    const float* Wqkv  = (const float*)d_in[1];
    const float* bqkv  = (const float*)d_in[2];
    const float* Wo    = (const float*)d_in[3];
    const float* gamma = (const float*)d_in[4];
    const float* beta  = (const float*)d_in[5];
    float* out = (float*)d_out;

    cudaFuncSetAttribute(attn_kernel,
                         cudaFuncAttributeMaxDynamicSharedMemorySize,
                         ATTN_SMEM_BYTES);

    qkv_gemm_kernel<<<dim3(N_QKV / 128, MROWS / 128), 256>>>(inp, Wqkv, bqkv);
    attn_kernel<<<dim3(TSEQ / 128, BH), 256, ATTN_SMEM_BYTES>>>();
    oproj_kernel<<<dim3(DMODEL / 128, MROWS / 128), 256>>>(inp, Wo);
    ln_kernel<<<MROWS / 8, 256>>>(gamma, beta, out);
}

// round 6
// speedup vs baseline: 2.3135x; 1.0050x over previous
#include <cuda_runtime.h>
#include <cuda_bf16.h>
#include <cstdint>

// Problem constants
#define BATCH   2
#define TSEQ    2048
#define NHEAD   16
#define DHEAD   64
#define DMODEL  1024
#define BH      (BATCH * NHEAD)        // 32
#define MROWS   (BATCH * TSEQ)         // 4096
#define N_QKV   (3 * NHEAD * DHEAD)    // 3072
#define ATTN_SCALE 0.125f              // 1/sqrt(64)
#define LN_EPS  1e-5f

// ---------------- scratch (static device globals; no allocations) ----------
__device__ float g_q [BH * TSEQ * DHEAD];   // [bh][t][d]
__device__ float g_k [BH * TSEQ * DHEAD];
__device__ float g_v [BH * TSEQ * DHEAD];
__device__ float g_av[BH * TSEQ * DHEAD];   // attention out, flat L = b*16+h
__device__ float g_y [MROWS * DMODEL];      // residual + attn_out (pre-LN)

// ---------------- bf16 helpers --------------------------------------------
__device__ __forceinline__ uint32_t pack_bf16(float lo, float hi) {
    __nv_bfloat162 h = __floats2bfloat162_rn(lo, hi);
    return *reinterpret_cast<uint32_t*>(&h);
}

// mma.sync m16n8k16 bf16: D = A*B + D  (fp32 accum)
// A frag (words, each = 2 bf16 along k):
//   a0=[row gid][word tg] a1=[gid+8][tg] a2=[gid][tg+4] a3=[gid+8][tg+4]
// B frag: b0=[n gid][word tg] b1=[gid][tg+4]   (k-major words, col-major B)
// C frag: c0=(gid,2tg) c1=(gid,2tg+1) c2=(gid+8,2tg) c3=(gid+8,2tg+1)
__device__ __forceinline__ void mma_bf16(float* c, const uint32_t* a,
                                         uint32_t b0, uint32_t b1) {
    asm volatile(
        "mma.sync.aligned.m16n8k16.row.col.f32.bf16.bf16.f32 "
        "{%0,%1,%2,%3}, {%4,%5,%6,%7}, {%8,%9}, {%0,%1,%2,%3};"
        : "+f"(c[0]), "+f"(c[1]), "+f"(c[2]), "+f"(c[3])
        : "r"(a[0]), "r"(a[1]), "r"(a[2]), "r"(a[3]), "r"(b0), "r"(b1));
}

#define GSTW 36   // smem row stride in 32-bit words (36 % 32 == 4 -> no conflicts)

// ===========================================================================
// Kernel 1: QKV GEMM (bf16 mma).  out[m][n] = inp[m][:]·Wqkv[n][:] + b[n]
// Block 128x128, 256 thr (8 warps as 4(m)x2(n)); warp tile 32x64.
// K-chunk = 64 bf16 (32 words). Epilogue scatters into g_q/g_k/g_v.
// ===========================================================================
__global__ __launch_bounds__(256) void qkv_gemm_kernel(
    const float* __restrict__ A,      // [4096][1024]
    const float* __restrict__ W,      // [3072][1024]
    const float* __restrict__ bias)   // [3072]
{
    __shared__ __align__(16) uint32_t As[128 * GSTW];
    __shared__ __align__(16) uint32_t Bs[128 * GSTW];

    const int tid  = threadIdx.x;
    const int lane = tid & 31;
    const int warp = tid >> 5;
    const int gid  = lane >> 2;
    const int tg   = lane & 3;
    const int wm   = warp & 3;        // m offset *32
    const int wn   = warp >> 2;       // n offset *64
    const int mBase = blockIdx.y * 128;
    const int nBase = blockIdx.x * 128;

    const int lrow = tid >> 1;        // 0..127
    const int lhw  = (tid & 1) * 16;  // word offset 0 or 16 (32 floats)

    const float* Ap = A + (size_t)(mBase + lrow) * DMODEL + (tid & 1) * 32;
    const float* Wp = W + (size_t)(nBase + lrow) * DMODEL + (tid & 1) * 32;

    float acc[2][8][4];
#pragma unroll
    for (int mi = 0; mi < 2; mi++)
#pragma unroll
        for (int ni = 0; ni < 8; ni++)
#pragma unroll
            for (int j = 0; j < 4; j++) acc[mi][ni][j] = 0.f;

    for (int k0 = 0; k0 < DMODEL; k0 += 64) {
#pragma unroll
        for (int i = 0; i < 8; i++) {
            float4 a = *(const float4*)(Ap + k0 + i * 4);
            float4 b = *(const float4*)(Wp + k0 + i * 4);
            *(uint2*)&As[lrow * GSTW + lhw + 2 * i] =
                make_uint2(pack_bf16(a.x, a.y), pack_bf16(a.z, a.w));
            *(uint2*)&Bs[lrow * GSTW + lhw + 2 * i] =
                make_uint2(pack_bf16(b.x, b.y), pack_bf16(b.z, b.w));
        }
        __syncthreads();
#pragma unroll
        for (int kk = 0; kk < 32; kk += 8) {     // 4 k16 steps
            uint32_t af[2][4];
#pragma unroll
            for (int mi = 0; mi < 2; mi++) {
                const uint32_t* qb = &As[(wm * 32 + mi * 16 + gid) * GSTW];
                af[mi][0] = qb[kk + tg];
                af[mi][1] = qb[8 * GSTW + kk + tg];
                af[mi][2] = qb[kk + tg + 4];
                af[mi][3] = qb[8 * GSTW + kk + tg + 4];
            }
#pragma unroll
            for (int ni = 0; ni < 8; ni++) {
                const uint32_t* bb = &Bs[(wn * 64 + ni * 8 + gid) * GSTW];
                uint32_t b0 = bb[kk + tg];
                uint32_t b1 = bb[kk + tg + 4];
                mma_bf16(acc[0][ni], af[0], b0, b1);
                mma_bf16(acc[1][ni], af[1], b0, b1);
            }
        }
        __syncthreads();
    }

    // epilogue: add bias, scatter into Q/K/V [bh][t][d]
#pragma unroll
    for (int mi = 0; mi < 2; mi++) {
        int r0 = mBase + wm * 32 + mi * 16 + gid;
        int r1 = r0 + 8;
        int bb0 = r0 >> 11, t0 = r0 & 2047;
        int bb1 = r1 >> 11, t1 = r1 & 2047;
#pragma unroll
        for (int ni = 0; ni < 8; ni++) {
            int n = nBase + wn * 64 + ni * 8 + tg * 2;
            int third = n >> 10;
            int nn = n & 1023;
            int h = nn >> 6, d = nn & 63;
            float* base = (third == 0) ? g_q : ((third == 1) ? g_k : g_v);
            float2 bi = *(const float2*)(bias + n);
            float2 lo = make_float2(acc[mi][ni][0] + bi.x, acc[mi][ni][1] + bi.y);
            float2 hi = make_float2(acc[mi][ni][2] + bi.x, acc[mi][ni][3] + bi.y);
            *(float2*)(base + ((bb0 * NHEAD + h) * TSEQ + t0) * DHEAD + d) = lo;
            *(float2*)(base + ((bb1 * NHEAD + h) * TSEQ + t1) * DHEAD + d) = hi;
        }
    }
}

// ===========================================================================
// Kernel 2: flash-style attention, bf16 mma.
// One CTA per (bh, 128-row q-block); 256 thr, 8 warps as 4(m)x2(n).
// Smem word layout (uint32 units):
//   Qb [128][36]  bf16 pairs along k(d)
//   Kb [64][36]   bf16 pairs along k(d)
//   Vt [64][36]   row=d, words = key pairs (V transposed, packed by key)
//   Sf [128][68]  fp32 scores
//   Pb [128][36]  bf16 prob pairs along key
//   rowm/rowl/rowc [128] each (fp32)
// ===========================================================================
#define QB_OFF  0
#define KB_OFF  (QB_OFF + 128 * GSTW)          // 4608
#define VT_OFF  (KB_OFF + 64 * GSTW)           // 6912
#define SF_OFF  (VT_OFF + 64 * GSTW)           // 9216 (float area)
#define PB_OFF  (SF_OFF + 128 * 68)            // 17920
#define RM_OFF  (PB_OFF + 128 * GSTW)          // 22528
#define RL_OFF  (RM_OFF + 128)
#define RC_OFF  (RL_OFF + 128)
#define ATTN_SMEM_WORDS (RC_OFF + 128)         // 22912
#define ATTN_SMEM_BYTES (ATTN_SMEM_WORDS * 4)  // 91648

__global__ __launch_bounds__(256) void attn_kernel()
{
    extern __shared__ __align__(16) uint32_t smw[];
    float* smf  = reinterpret_cast<float*>(smw);
    float* rowm = smf + RM_OFF;
    float* rowl = smf + RL_OFF;
    float* rowc = smf + RC_OFF;

    const int tid  = threadIdx.x;
    const int lane = tid & 31;
    const int warp = tid >> 5;
    const int gid  = lane >> 2;
    const int tg   = lane & 3;
    const int wm   = warp & 3;       // row quarter (*32)
    const int wn   = warp >> 2;      // col half (*32)
    const int bh   = blockIdx.y;
    const int q0   = blockIdx.x * 128;

    float oacc[2][4][4];
#pragma unroll
    for (int mi = 0; mi < 2; mi++)
#pragma unroll
        for (int ni = 0; ni < 4; ni++)
#pragma unroll
            for (int j = 0; j < 4; j++) oacc[mi][ni][j] = 0.f;

    if (tid < 128) { rowm[tid] = -1e30f; rowl[tid] = 0.f; }

    // ---- load Q tile as bf16 pairs: Qb[m][d/2] ----
    {
        const int qr = tid >> 1;
        const int hb = tid & 1;
        const float* gq = g_q + (bh * TSEQ + q0 + qr) * DHEAD + hb * 32;
        uint32_t* qrow = &smw[QB_OFF + qr * GSTW + hb * 16];
#pragma unroll
        for (int i = 0; i < 8; i++) {
            float4 v = *(const float4*)(gq + i * 4);
            *(uint2*)&qrow[2 * i] =
                make_uint2(pack_bf16(v.x, v.y), pack_bf16(v.z, v.w));
        }
    }

    for (int kt = 0; kt < TSEQ / 64; kt++) {
        __syncthreads();   // prev iter done reading Kb/Vt/Pb; Q visible on it0

        // ---- K tile: Kb[key][d/2] ----
        {
            const int kr = tid >> 2;
            const int qd = tid & 3;
            const float* gk = g_k + (bh * TSEQ + kt * 64 + kr) * DHEAD + qd * 16;
            uint32_t* krow = &smw[KB_OFF + kr * GSTW + qd * 8];
#pragma unroll
            for (int i = 0; i < 4; i++) {
                float4 v = *(const float4*)(gk + i * 4);
                *(uint2*)&krow[2 * i] =
                    make_uint2(pack_bf16(v.x, v.y), pack_bf16(v.z, v.w));
            }
        }
        // ---- V tile transposed+packed: Vt[d][keypair] ----
        {
            const int kp = tid & 31;           // key pair index
            const int db = (tid >> 5) * 8;     // 8 d values
            const float* gv0 = g_v + (bh * TSEQ + kt * 64 + 2 * kp) * DHEAD + db;
            const float* gv1 = gv0 + DHEAD;
#pragma unroll
            for (int i = 0; i < 8; i += 4) {
                float4 v0 = *(const float4*)(gv0 + i);
                float4 v1 = *(const float4*)(gv1 + i);
                smw[VT_OFF + (db + i + 0) * GSTW + kp] = pack_bf16(v0.x, v1.x);
                smw[VT_OFF + (db + i + 1) * GSTW + kp] = pack_bf16(v0.y, v1.y);
                smw[VT_OFF + (db + i + 2) * GSTW + kp] = pack_bf16(v0.z, v1.z);
                smw[VT_OFF + (db + i + 3) * GSTW + kp] = pack_bf16(v0.w, v1.w);
            }
        }
        __syncthreads();

        // ---- GEMM1: S[128,64] = Q·K^T (warp tile 32x32) ----
        {
            float s[2][4][4];
#pragma unroll
            for (int mi = 0; mi < 2; mi++)
#pragma unroll
                for (int ni = 0; ni < 4; ni++)
#pragma unroll
                    for (int j = 0; j < 4; j++) s[mi][ni][j] = 0.f;
#pragma unroll
            for (int kk = 0; kk < 32; kk += 8) {
                uint32_t af[2][4];
#pragma unroll
                for (int mi = 0; mi < 2; mi++) {
                    const uint32_t* qb = &smw[QB_OFF + (wm * 32 + mi * 16 + gid) * GSTW];
                    af[mi][0] = qb[kk + tg];
                    af[mi][1] = qb[8 * GSTW + kk + tg];
                    af[mi][2] = qb[kk + tg + 4];
                    af[mi][3] = qb[8 * GSTW + kk + tg + 4];
                }
#pragma unroll
                for (int ni = 0; ni < 4; ni++) {
                    const uint32_t* kb = &smw[KB_OFF + (wn * 32 + ni * 8 + gid) * GSTW];
                    uint32_t b0 = kb[kk + tg];
                    uint32_t b1 = kb[kk + tg + 4];
                    mma_bf16(s[0][ni], af[0], b0, b1);
                    mma_bf16(s[1][ni], af[1], b0, b1);
                }
            }
            // stage scaled fp32 scores
#pragma unroll
            for (int mi = 0; mi < 2; mi++) {
                int r = wm * 32 + mi * 16 + gid;
#pragma unroll
                for (int ni = 0; ni < 4; ni++) {
                    int cc = wn * 32 + ni * 8 + tg * 2;
                    *(float2*)&smf[SF_OFF + r * 68 + cc] =
                        make_float2(s[mi][ni][0] * ATTN_SCALE, s[mi][ni][1] * ATTN_SCALE);
                    *(float2*)&smf[SF_OFF + (r + 8) * 68 + cc] =
                        make_float2(s[mi][ni][2] * ATTN_SCALE, s[mi][ni][3] * ATTN_SCALE);
                }
            }
        }
        __syncthreads();

        // ---- online softmax: 2 threads per row, write bf16 probs ----
        {
            const int row = tid >> 1;
            const int cb  = (tid & 1) * 32;
            const float* srow = &smf[SF_OFF + row * 68 + cb];
            float mprev = rowm[row];
            float mx = mprev;
#pragma unroll 8
            for (int c = 0; c < 32; c++) mx = fmaxf(mx, srow[c]);
            mx = fmaxf(mx, __shfl_xor_sync(0xFFFFFFFFu, mx, 1));
            float corr = __expf(mprev - mx);
            float sum = 0.f;
            float p[32];
#pragma unroll 8
            for (int c = 0; c < 32; c++) {
                p[c] = __expf(srow[c] - mx);
                sum += p[c];
            }
            uint32_t* prow = &smw[PB_OFF + row * GSTW + cb / 2];
#pragma unroll
            for (int j = 0; j < 16; j++)
                prow[j] = pack_bf16(p[2 * j], p[2 * j + 1]);
            sum += __shfl_xor_sync(0xFFFFFFFFu, sum, 1);
            if ((tid & 1) == 0) {
                rowl[row] = rowl[row] * corr + sum;
                rowm[row] = mx;
                rowc[row] = corr;
            }
        }
        __syncthreads();

        // ---- GEMM2: O = O*corr + P·V (warp tile 32(m)x32(d)) ----
#pragma unroll
        for (int mi = 0; mi < 2; mi++) {
            int r = wm * 32 + mi * 16 + gid;
            float cl = rowc[r], ch = rowc[r + 8];
#pragma unroll
            for (int ni = 0; ni < 4; ni++) {
                oacc[mi][ni][0] *= cl; oacc[mi][ni][1] *= cl;
                oacc[mi][ni][2] *= ch; oacc[mi][ni][3] *= ch;
            }
        }
#pragma unroll
        for (int kk = 0; kk < 32; kk += 8) {
            uint32_t af[2][4];
#pragma unroll
            for (int mi = 0; mi < 2; mi++) {
                const uint32_t* pb = &smw[PB_OFF + (wm * 32 + mi * 16 + gid) * GSTW];
                af[mi][0] = pb[kk + tg];
                af[mi][1] = pb[8 * GSTW + kk + tg];
                af[mi][2] = pb[kk + tg + 4];
                af[mi][3] = pb[8 * GSTW + kk + tg + 4];
            }
#pragma unroll
            for (int ni = 0; ni < 4; ni++) {
                const uint32_t* vb = &smw[VT_OFF + (wn * 32 + ni * 8 + gid) * GSTW];
                uint32_t b0 = vb[kk + tg];
                uint32_t b1 = vb[kk + tg + 4];
                mma_bf16(oacc[0][ni], af[0], b0, b1);
                mma_bf16(oacc[1][ni], af[1], b0, b1);
            }
        }
    }

    // ---- writeback normalized output ----
#pragma unroll
    for (int mi = 0; mi < 2; mi++) {
        int r = wm * 32 + mi * 16 + gid;
        float il = 1.0f / rowl[r];
        float ih = 1.0f / rowl[r + 8];
#pragma unroll
        for (int ni = 0; ni < 4; ni++) {
            int cc = wn * 32 + ni * 8 + tg * 2;
            float2 lo = make_float2(oacc[mi][ni][0] * il, oacc[mi][ni][1] * il);
            float2 hi = make_float2(oacc[mi][ni][2] * ih, oacc[mi][ni][3] * ih);
            *(float2*)(g_av + (bh * TSEQ + q0 + r) * DHEAD + cc) = lo;
            *(float2*)(g_av + (bh * TSEQ + q0 + r + 8) * DHEAD + cc) = hi;
        }
    }
}

// ===========================================================================
// Kernel 3: O projection + residual (bf16 mma).
// y[m][n] = sum_c av_perm[m][c]·Wo[n][c] + inp[m][n],
// av_perm[(b2,t)][h2*64+d] = g_av[h2*2+b2][t][d]  (reference (H,B)-view quirk)
// With k-chunk = 64, head index h2 == chunk index exactly.
// ===========================================================================
__global__ __launch_bounds__(256) void oproj_kernel(
    const float* __restrict__ inp,    // [4096][1024]
    const float* __restrict__ Wo)     // [1024][1024]
{
    __shared__ __align__(16) uint32_t As[128 * GSTW];
    __shared__ __align__(16) uint32_t Bs[128 * GSTW];

    const int tid  = threadIdx.x;
    const int lane = tid & 31;
    const int warp = tid >> 5;
    const int gid  = lane >> 2;
    const int tg   = lane & 3;
    const int wm   = warp & 3;
    const int wn   = warp >> 2;
    const int mBase = blockIdx.y * 128;
    const int nBase = blockIdx.x * 128;

    const int lrow = tid >> 1;
    const int lhw  = (tid & 1) * 16;
    const int lcb  = (tid & 1) * 32;

    const int m  = mBase + lrow;
    const int b2 = m >> 11;
    const int t  = m & 2047;
    const float* Wp = Wo + (size_t)(nBase + lrow) * DMODEL + lcb;

    float acc[2][8][4];
#pragma unroll
    for (int mi = 0; mi < 2; mi++)
#pragma unroll
        for (int ni = 0; ni < 8; ni++)
#pragma unroll
            for (int j = 0; j < 4; j++) acc[mi][ni][j] = 0.f;

    for (int kt = 0; kt < 16; kt++) {
        // A row for this chunk comes from head h2 = kt
        const float* avp = g_av + ((size_t)(kt * BATCH + b2) * TSEQ + t) * DHEAD + lcb;
        const float* wp  = Wp + kt * 64;
#pragma unroll
        for (int i = 0; i < 8; i++) {
            float4 a = *(const float4*)(avp + i * 4);
            float4 b = *(const float4*)(wp + i * 4);
            *(uint2*)&As[lrow * GSTW + lhw + 2 * i] =
                make_uint2(pack_bf16(a.x, a.y), pack_bf16(a.z, a.w));
            *(uint2*)&Bs[lrow * GSTW + lhw + 2 * i] =
                make_uint2(pack_bf16(b.x, b.y), pack_bf16(b.z, b.w));
        }
        __syncthreads();
#pragma unroll
        for (int kk = 0; kk < 32; kk += 8) {
            uint32_t af[2][4];
#pragma unroll
            for (int mi = 0; mi < 2; mi++) {
                const uint32_t* qb = &As[(wm * 32 + mi * 16 + gid) * GSTW];
                af[mi][0] = qb[kk + tg];
                af[mi][1] = qb[8 * GSTW + kk + tg];
                af[mi][2] = qb[kk + tg + 4];
                af[mi][3] = qb[8 * GSTW + kk + tg + 4];
            }
#pragma unroll
            for (int ni = 0; ni < 8; ni++) {
                const uint32_t* bb = &Bs[(wn * 64 + ni * 8 + gid) * GSTW];
                uint32_t b0 = bb[kk + tg];
                uint32_t b1 = bb[kk + tg + 4];
                mma_bf16(acc[0][ni], af[0], b0, b1);
                mma_bf16(acc[1][ni], af[1], b0, b1);
            }
        }
        __syncthreads();
    }

    // epilogue: residual add, write g_y
#pragma unroll
    for (int mi = 0; mi < 2; mi++) {
        int r0 = mBase + wm * 32 + mi * 16 + gid;
        int r1 = r0 + 8;
#pragma unroll
        for (int ni = 0; ni < 8; ni++) {
            int n = nBase + wn * 64 + ni * 8 + tg * 2;
            float2 i0 = *(const float2*)(inp + (size_t)r0 * DMODEL + n);
            float2 i1 = *(const float2*)(inp + (size_t)r1 * DMODEL + n);
            float2 lo = make_float2(acc[mi][ni][0] + i0.x, acc[mi][ni][1] + i0.y);
            float2 hi = make_float2(acc[mi][ni][2] + i1.x, acc[mi][ni][3] + i1.y);
            *(float2*)(g_y + (size_t)r0 * DMODEL + n) = lo;
            *(float2*)(g_y + (size_t)r1 * DMODEL + n) = hi;
        }
    }
}

// ===========================================================================
// Kernel 4: LayerNorm. One warp per row of 1024.
// ===========================================================================
__global__ __launch_bounds__(256) void ln_kernel(
    const float* __restrict__ gamma,
    const float* __restrict__ beta,
    float* __restrict__ out)
{
    const int row  = blockIdx.x * 8 + (threadIdx.x >> 5);
    const int lane = threadIdx.x & 31;
    const float* x = g_y + (size_t)row * DMODEL;

    float4 v[8];
    float s1 = 0.f, s2 = 0.f;
#pragma unroll
    for (int i = 0; i < 8; i++) {
        v[i] = *(const float4*)(x + lane * 4 + i * 128);
        s1 += v[i].x + v[i].y + v[i].z + v[i].w;
        s2 += v[i].x * v[i].x + v[i].y * v[i].y + v[i].z * v[i].z + v[i].w * v[i].w;
    }
#pragma unroll
    for (int off = 16; off > 0; off >>= 1) {
        s1 += __shfl_xor_sync(0xFFFFFFFFu, s1, off);
        s2 += __shfl_xor_sync(0xFFFFFFFFu, s2, off);
    }
    float mu   = s1 * (1.0f / DMODEL);
    float var  = s2 * (1.0f / DMODEL) - mu * mu;
    float rstd = rsqrtf(var + LN_EPS);

    float* o = out + (size_t)row * DMODEL;
#pragma unroll
    for (int i = 0; i < 8; i++) {
        int cbase = lane * 4 + i * 128;
        float4 g = *(const float4*)(gamma + cbase);
        float4 b = *(const float4*)(beta + cbase);
        float4 r;
        r.x = (v[i].x - mu) * rstd * g.x + b.x;
        r.y = (v[i].y - mu) * rstd * g.y + b.y;
        r.z = (v[i].z - mu) * rstd * g.z + b.z;
        r.w = (v[i].w - mu) * rstd * g.w + b.w;
        *(float4*)(o + cbase) = r;
    }
}

// ===========================================================================
extern "C" void kernel_launch(void* const* d_in, const int* in_sizes, int n_in,
                              void* d_out, int out_size)
{
    const float* inp   = (const float*)d_in[0];
    const float* Wqkv  = (const float*)d_in[1];
    const float* bqkv  = (const float*)d_in[2];
    const float* Wo    = (const float*)d_in[3];
    const float* gamma = (const float*)d_in[4];
    const float* beta  = (const float*)d_in[5];
    float* out = (float*)d_out;

    cudaFuncSetAttribute(attn_kernel,
                         cudaFuncAttributeMaxDynamicSharedMemorySize,
                         ATTN_SMEM_BYTES);

    qkv_gemm_kernel<<<dim3(N_QKV / 128, MROWS / 128), 256>>>(inp, Wqkv, bqkv);
    attn_kernel<<<dim3(TSEQ / 128, BH), 256, ATTN_SMEM_BYTES>>>();
    oproj_kernel<<<dim3(DMODEL / 128, MROWS / 128), 256>>>(inp, Wo);
    ln_kernel<<<MROWS / 8, 256>>>(gamma, beta, out);
}

// round 8
// speedup vs baseline: 4.0532x; 1.7520x over previous
#include <cuda_runtime.h>
#include <cuda_bf16.h>
#include <cstdint>

// Problem constants
#define BATCH   2
#define TSEQ    2048
#define NHEAD   16
#define DHEAD   64
#define DMODEL  1024
#define BH      (BATCH * NHEAD)        // 32
#define MROWS   (BATCH * TSEQ)         // 4096
#define N_QKV   (3 * NHEAD * DHEAD)    // 3072
#define ATTN_SCALE 0.125f              // 1/sqrt(64)
#define LN_EPS  1e-5f

// ---------------- scratch (static device globals; no allocations) ----------
// bf16 pair-packed (uint32 = 2 bf16)
__device__ __align__(16) uint32_t g_inp_bf [MROWS * DMODEL / 2];   // [4096][512]
__device__ __align__(16) uint32_t g_wqkv_bf[N_QKV * DMODEL / 2];   // [3072][512]
__device__ __align__(16) uint32_t g_wo_bf  [DMODEL * DMODEL / 2];  // [1024][512]
__device__ __align__(16) uint32_t g_qw [BH * TSEQ * 32];  // [bh][t][d/2]
__device__ __align__(16) uint32_t g_kw [BH * TSEQ * 32];
__device__ __align__(16) uint32_t g_vw [BH * TSEQ * 32];
__device__ __align__(16) uint32_t g_avw[BH * TSEQ * 32];  // attn out, flat L=b*16+h
__device__ float g_y[MROWS * DMODEL];                     // pre-LN fp32

// ---------------- helpers --------------------------------------------------
__device__ __forceinline__ uint32_t pack_bf16(float lo, float hi) {
    __nv_bfloat162 h = __floats2bfloat162_rn(lo, hi);
    return *reinterpret_cast<uint32_t*>(&h);
}

__device__ __forceinline__ uint32_t smem_u32(const void* p) {
    uint32_t a;
    asm("{ .reg .u64 t; cvta.to.shared.u64 t, %1; cvt.u32.u64 %0, t; }"
        : "=r"(a) : "l"(p));
    return a;
}

__device__ __forceinline__ void cp16(uint32_t s, const void* g) {
    asm volatile("cp.async.cg.shared.global [%0], [%1], 16;"
                 :: "r"(s), "l"(g) : "memory");
}
#define CP_COMMIT() asm volatile("cp.async.commit_group;" ::: "memory")
#define CP_WAIT(n)  asm volatile("cp.async.wait_group %0;" :: "n"(n) : "memory")

// mma.sync m16n8k16 bf16 (fp32 accum); frag layouts as in R5.
__device__ __forceinline__ void mma_bf16(float* c, const uint32_t* a,
                                         uint32_t b0, uint32_t b1) {
    asm volatile(
        "mma.sync.aligned.m16n8k16.row.col.f32.bf16.bf16.f32 "
        "{%0,%1,%2,%3}, {%4,%5,%6,%7}, {%8,%9}, {%0,%1,%2,%3};"
        : "+f"(c[0]), "+f"(c[1]), "+f"(c[2]), "+f"(c[3])
        : "r"(a[0]), "r"(a[1]), "r"(a[2]), "r"(a[3]), "r"(b0), "r"(b1));
}

#define GSTW 36   // smem row stride in words (36 % 32 == 4 -> conflict-free)

// ===========================================================================
// Kernel 0: one-time fp32 -> bf16 pre-convert of inp / W_qkv / W_o.
// ===========================================================================
#define CVT_T1 (MROWS * DMODEL / 4)    // 1048576 float4s
#define CVT_T2 (N_QKV * DMODEL / 4)    //  786432
#define CVT_T3 (DMODEL * DMODEL / 4)   //  262144
#define CVT_TOTAL (CVT_T1 + CVT_T2 + CVT_T3)

__global__ __launch_bounds__(256) void cvt_kernel(
    const float* __restrict__ inp,
    const float* __restrict__ wqkv,
    const float* __restrict__ wo)
{
    int idx = blockIdx.x * 256 + threadIdx.x;
    const float4* src;
    uint2* dst;
    int li;
    if (idx < CVT_T1) {
        src = (const float4*)inp;  dst = (uint2*)g_inp_bf;  li = idx;
    } else if (idx < CVT_T1 + CVT_T2) {
        src = (const float4*)wqkv; dst = (uint2*)g_wqkv_bf; li = idx - CVT_T1;
    } else {
        src = (const float4*)wo;   dst = (uint2*)g_wo_bf;   li = idx - CVT_T1 - CVT_T2;
    }
    float4 v = src[li];
    dst[li] = make_uint2(pack_bf16(v.x, v.y), pack_bf16(v.z, v.w));
}

// ===========================================================================
// Kernel 1: QKV GEMM, bf16 mma + cp.async double-buffered pipeline.
// Block 128x128, 256 thr (8 warps 4x2); warp tile 32x64; k-chunk 64 bf16.
// SMEM (bytes): A0@0 A1@18432 B0@36864 B1@55296, each 128 rows x 144B.
// Tile copy = 128 rows x 8 x 16B = 1024 cp16s per matrix -> p<4 per thread.
// ===========================================================================
#define GEMM_SMEM_BYTES 73728

__device__ __forceinline__ void gemm_issue_tile(
    uint32_t sbase, const char* gA, const char* gB, int kt, int buf, int tid)
{
    const uint32_t sa  = sbase + buf * 18432;
    const uint32_t sbb = sbase + 36864 + buf * 18432;
#pragma unroll
    for (int p = 0; p < 4; p++) {                 // FIX: 4 passes (1024 copies)
        int c = tid + p * 256;
        int row = c >> 3, col = c & 7;
        cp16(sa  + row * 144 + col * 16, gA + (size_t)row * 2048 + kt * 128 + col * 16);
        cp16(sbb + row * 144 + col * 16, gB + (size_t)row * 2048 + kt * 128 + col * 16);
    }
}

__global__ __launch_bounds__(256) void qkv_gemm_kernel(
    const float* __restrict__ bias)   // [3072]
{
    extern __shared__ __align__(16) uint32_t smw[];
    const uint32_t sb = smem_u32(smw);

    const int tid  = threadIdx.x;
    const int lane = tid & 31;
    const int warp = tid >> 5;
    const int gid  = lane >> 2;
    const int tg   = lane & 3;
    const int wm   = warp & 3;
    const int wn   = warp >> 2;
    const int mBase = blockIdx.y * 128;
    const int nBase = blockIdx.x * 128;

    const char* gA = (const char*)g_inp_bf  + (size_t)mBase * 2048;
    const char* gB = (const char*)g_wqkv_bf + (size_t)nBase * 2048;

    float acc[2][8][4];
#pragma unroll
    for (int mi = 0; mi < 2; mi++)
#pragma unroll
        for (int ni = 0; ni < 8; ni++)
#pragma unroll
            for (int j = 0; j < 4; j++) acc[mi][ni][j] = 0.f;

    gemm_issue_tile(sb, gA, gB, 0, 0, tid);
    CP_COMMIT();

    for (int kt = 0; kt < 16; kt++) {
        const int buf = kt & 1;
        if (kt < 15) {
            gemm_issue_tile(sb, gA, gB, kt + 1, buf ^ 1, tid);
            CP_COMMIT();
            CP_WAIT(1);
        } else {
            CP_WAIT(0);
        }
        __syncthreads();

        const uint32_t* As = smw + buf * 4608;
        const uint32_t* Bs = smw + 9216 + buf * 4608;
#pragma unroll
        for (int kk = 0; kk < 32; kk += 8) {
            uint32_t af[2][4];
#pragma unroll
            for (int mi = 0; mi < 2; mi++) {
                const uint32_t* qb = &As[(wm * 32 + mi * 16 + gid) * GSTW];
                af[mi][0] = qb[kk + tg];
                af[mi][1] = qb[8 * GSTW + kk + tg];
                af[mi][2] = qb[kk + tg + 4];
                af[mi][3] = qb[8 * GSTW + kk + tg + 4];
            }
#pragma unroll
            for (int ni = 0; ni < 8; ni++) {
                const uint32_t* bb = &Bs[(wn * 64 + ni * 8 + gid) * GSTW];
                uint32_t b0 = bb[kk + tg];
                uint32_t b1 = bb[kk + tg + 4];
                mma_bf16(acc[0][ni], af[0], b0, b1);
                mma_bf16(acc[1][ni], af[1], b0, b1);
            }
        }
        __syncthreads();
    }

    // epilogue: +bias, pack bf16 pair, scatter into q/k/v word arrays
#pragma unroll
    for (int mi = 0; mi < 2; mi++) {
        int r0 = mBase + wm * 32 + mi * 16 + gid;
        int r1 = r0 + 8;
        int bb0 = r0 >> 11, t0 = r0 & 2047;
        int bb1 = r1 >> 11, t1 = r1 & 2047;
#pragma unroll
        for (int ni = 0; ni < 8; ni++) {
            int n = nBase + wn * 64 + ni * 8 + tg * 2;
            int third = n >> 10;
            int nn = n & 1023;
            int h = nn >> 6, d = nn & 63;
            uint32_t* base = (third == 0) ? g_qw : ((third == 1) ? g_kw : g_vw);
            float2 bi = *(const float2*)(bias + n);
            base[((bb0 * NHEAD + h) * TSEQ + t0) * 32 + d / 2] =
                pack_bf16(acc[mi][ni][0] + bi.x, acc[mi][ni][1] + bi.y);
            base[((bb1 * NHEAD + h) * TSEQ + t1) * 32 + d / 2] =
                pack_bf16(acc[mi][ni][2] + bi.x, acc[mi][ni][3] + bi.y);
        }
    }
}

// ===========================================================================
// Kernel 2: flash-style attention, bf16 mma, bf16 global I/O.
// One CTA per (bh, 128-row q-block); 256 thr, 8 warps 4(m)x2(n).
// ===========================================================================
#define QB_OFF  0
#define KB_OFF  (QB_OFF + 128 * GSTW)          // 4608
#define VT_OFF  (KB_OFF + 64 * GSTW)           // 6912
#define SF_OFF  (VT_OFF + 64 * GSTW)           // 9216 (fp32 scores)
#define PB_OFF  (SF_OFF + 128 * 68)            // 17920
#define RM_OFF  (PB_OFF + 128 * GSTW)          // 22528
#define RL_OFF  (RM_OFF + 128)
#define RC_OFF  (RL_OFF + 128)
#define ATTN_SMEM_WORDS (RC_OFF + 128)
#define ATTN_SMEM_BYTES (ATTN_SMEM_WORDS * 4)  // 91648

__global__ __launch_bounds__(256) void attn_kernel()
{
    extern __shared__ __align__(16) uint32_t smw[];
    const uint32_t sb = smem_u32(smw);
    float* smf  = reinterpret_cast<float*>(smw);
    float* rowm = smf + RM_OFF;
    float* rowl = smf + RL_OFF;
    float* rowc = smf + RC_OFF;

    const int tid  = threadIdx.x;
    const int lane = tid & 31;
    const int warp = tid >> 5;
    const int gid  = lane >> 2;
    const int tg   = lane & 3;
    const int wm   = warp & 3;
    const int wn   = warp >> 2;
    const int bh   = blockIdx.y;
    const int q0   = blockIdx.x * 128;

    float oacc[2][4][4];
#pragma unroll
    for (int mi = 0; mi < 2; mi++)
#pragma unroll
        for (int ni = 0; ni < 4; ni++)
#pragma unroll
            for (int j = 0; j < 4; j++) oacc[mi][ni][j] = 0.f;

    if (tid < 128) { rowm[tid] = -1e30f; rowl[tid] = 0.f; }

    // ---- load Q tile (already bf16 pairs) ----
    {
        const int qr = tid >> 1;
        const int hb = (tid & 1) * 16;
        const uint32_t* gq = g_qw + (size_t)(bh * TSEQ + q0 + qr) * 32 + hb;
        uint32_t* qrow = &smw[QB_OFF + qr * GSTW + hb];
#pragma unroll
        for (int i = 0; i < 4; i++)
            *(uint4*)&qrow[i * 4] = *(const uint4*)(gq + i * 4);
    }

    for (int kt = 0; kt < TSEQ / 64; kt++) {
        __syncthreads();   // prior iter done with Kb/Vt/Pb; Q visible at kt=0

        // ---- K tile via cp.async: 64 rows x 128B (512 cp16s) ----
        {
            const char* gk = (const char*)g_kw + (size_t)(bh * TSEQ + kt * 64) * 128;
            const uint32_t kbb = sb + KB_OFF * 4;
#pragma unroll
            for (int p = 0; p < 2; p++) {
                int c = tid + p * 256;
                int row = c >> 3, col = c & 7;
                cp16(kbb + row * 144 + col * 16, gk + row * 128 + col * 16);
            }
            CP_COMMIT();
        }
        // ---- V tile: load bf16, transpose into key-pair words ----
        {
            const int kp = tid & 31;
            const int db = (tid >> 5) * 8;
            const uint32_t* gv0 = g_vw + (size_t)(bh * TSEQ + kt * 64 + 2 * kp) * 32 + db / 2;
            uint4 a = *(const uint4*)gv0;
            uint4 b = *(const uint4*)(gv0 + 32);
            uint32_t* vt = &smw[VT_OFF + db * GSTW + kp];
            vt[0 * GSTW] = __byte_perm(a.x, b.x, 0x5410);
            vt[1 * GSTW] = __byte_perm(a.x, b.x, 0x7632);
            vt[2 * GSTW] = __byte_perm(a.y, b.y, 0x5410);
            vt[3 * GSTW] = __byte_perm(a.y, b.y, 0x7632);
            vt[4 * GSTW] = __byte_perm(a.z, b.z, 0x5410);
            vt[5 * GSTW] = __byte_perm(a.z, b.z, 0x7632);
            vt[6 * GSTW] = __byte_perm(a.w, b.w, 0x5410);
            vt[7 * GSTW] = __byte_perm(a.w, b.w, 0x7632);
        }
        CP_WAIT(0);
        __syncthreads();

        // ---- GEMM1: S[128,64] = Q·K^T ----
        {
            float s[2][4][4];
#pragma unroll
            for (int mi = 0; mi < 2; mi++)
#pragma unroll
                for (int ni = 0; ni < 4; ni++)
#pragma unroll
                    for (int j = 0; j < 4; j++) s[mi][ni][j] = 0.f;
#pragma unroll
            for (int kk = 0; kk < 32; kk += 8) {
                uint32_t af[2][4];
#pragma unroll
                for (int mi = 0; mi < 2; mi++) {
                    const uint32_t* qb = &smw[QB_OFF + (wm * 32 + mi * 16 + gid) * GSTW];
                    af[mi][0] = qb[kk + tg];
                    af[mi][1] = qb[8 * GSTW + kk + tg];
                    af[mi][2] = qb[kk + tg + 4];
                    af[mi][3] = qb[8 * GSTW + kk + tg + 4];
                }
#pragma unroll
                for (int ni = 0; ni < 4; ni++) {
                    const uint32_t* kb = &smw[KB_OFF + (wn * 32 + ni * 8 + gid) * GSTW];
                    uint32_t b0 = kb[kk + tg];
                    uint32_t b1 = kb[kk + tg + 4];
                    mma_bf16(s[0][ni], af[0], b0, b1);
                    mma_bf16(s[1][ni], af[1], b0, b1);
                }
            }
#pragma unroll
            for (int mi = 0; mi < 2; mi++) {
                int r = wm * 32 + mi * 16 + gid;
#pragma unroll
                for (int ni = 0; ni < 4; ni++) {
                    int cc = wn * 32 + ni * 8 + tg * 2;
                    *(float2*)&smf[SF_OFF + r * 68 + cc] =
                        make_float2(s[mi][ni][0] * ATTN_SCALE, s[mi][ni][1] * ATTN_SCALE);
                    *(float2*)&smf[SF_OFF + (r + 8) * 68 + cc] =
                        make_float2(s[mi][ni][2] * ATTN_SCALE, s[mi][ni][3] * ATTN_SCALE);
                }
            }
        }
        __syncthreads();

        // ---- online softmax: 2 threads/row ----
        {
            const int row = tid >> 1;
            const int cb  = (tid & 1) * 32;
            const float* srow = &smf[SF_OFF + row * 68 + cb];
            float mprev = rowm[row];
            float mx = mprev;
#pragma unroll 8
            for (int c = 0; c < 32; c++) mx = fmaxf(mx, srow[c]);
            mx = fmaxf(mx, __shfl_xor_sync(0xFFFFFFFFu, mx, 1));
            float corr = __expf(mprev - mx);
            float sum = 0.f;
            float p[32];
#pragma unroll 8
            for (int c = 0; c < 32; c++) {
                p[c] = __expf(srow[c] - mx);
                sum += p[c];
            }
            uint32_t* prow = &smw[PB_OFF + row * GSTW + cb / 2];
#pragma unroll
            for (int j = 0; j < 16; j++)
                prow[j] = pack_bf16(p[2 * j], p[2 * j + 1]);
            sum += __shfl_xor_sync(0xFFFFFFFFu, sum, 1);
            if ((tid & 1) == 0) {
                rowl[row] = rowl[row] * corr + sum;
                rowm[row] = mx;
                rowc[row] = corr;
            }
        }
        __syncthreads();

        // ---- GEMM2: O = O*corr + P·V ----
#pragma unroll
        for (int mi = 0; mi < 2; mi++) {
            int r = wm * 32 + mi * 16 + gid;
            float cl = rowc[r], ch = rowc[r + 8];
#pragma unroll
            for (int ni = 0; ni < 4; ni++) {
                oacc[mi][ni][0] *= cl; oacc[mi][ni][1] *= cl;
                oacc[mi][ni][2] *= ch; oacc[mi][ni][3] *= ch;
            }
        }
#pragma unroll
        for (int kk = 0; kk < 32; kk += 8) {
            uint32_t af[2][4];
#pragma unroll
            for (int mi = 0; mi < 2; mi++) {
                const uint32_t* pb = &smw[PB_OFF + (wm * 32 + mi * 16 + gid) * GSTW];
                af[mi][0] = pb[kk + tg];
                af[mi][1] = pb[8 * GSTW + kk + tg];
                af[mi][2] = pb[kk + tg + 4];
                af[mi][3] = pb[8 * GSTW + kk + tg + 4];
            }
#pragma unroll
            for (int ni = 0; ni < 4; ni++) {
                const uint32_t* vb = &smw[VT_OFF + (wn * 32 + ni * 8 + gid) * GSTW];
                uint32_t b0 = vb[kk + tg];
                uint32_t b1 = vb[kk + tg + 4];
                mma_bf16(oacc[0][ni], af[0], b0, b1);
                mma_bf16(oacc[1][ni], af[1], b0, b1);
            }
        }
    }

    // ---- writeback normalized bf16 output ----
#pragma unroll
    for (int mi = 0; mi < 2; mi++) {
        int r = wm * 32 + mi * 16 + gid;
        float il = 1.0f / rowl[r];
        float ih = 1.0f / rowl[r + 8];
#pragma unroll
        for (int ni = 0; ni < 4; ni++) {
            int cc = wn * 32 + ni * 8 + tg * 2;
            g_avw[(size_t)(bh * TSEQ + q0 + r) * 32 + cc / 2] =
                pack_bf16(oacc[mi][ni][0] * il, oacc[mi][ni][1] * il);
            g_avw[(size_t)(bh * TSEQ + q0 + r + 8) * 32 + cc / 2] =
                pack_bf16(oacc[mi][ni][2] * ih, oacc[mi][ni][3] * ih);
        }
    }
}

// ===========================================================================
// Kernel 3: O-projection + residual, bf16 mma + cp.async pipeline.
// A = av_perm (reference (H,B)-view quirk: chunk kt -> head h2 = kt).
// ===========================================================================
__global__ __launch_bounds__(256) void oproj_kernel(
    const float* __restrict__ inp)    // [4096][1024] fp32 (residual)
{
    extern __shared__ __align__(16) uint32_t smw[];
    const uint32_t sb = smem_u32(smw);

    const int tid  = threadIdx.x;
    const int lane = tid & 31;
    const int warp = tid >> 5;
    const int gid  = lane >> 2;
    const int tg   = lane & 3;
    const int wm   = warp & 3;
    const int wn   = warp >> 2;
    const int mBase = blockIdx.y * 128;
    const int nBase = blockIdx.x * 128;

    const char* gB = (const char*)g_wo_bf + (size_t)nBase * 2048;

    float acc[2][8][4];
#pragma unroll
    for (int mi = 0; mi < 2; mi++)
#pragma unroll
        for (int ni = 0; ni < 8; ni++)
#pragma unroll
            for (int j = 0; j < 4; j++) acc[mi][ni][j] = 0.f;

    auto issue = [&](int kt, int buf) {
        const uint32_t sa  = sb + buf * 18432;
        const uint32_t sbb = sb + 36864 + buf * 18432;
#pragma unroll
        for (int p = 0; p < 4; p++) {             // FIX: 4 passes (1024 copies)
            int c = tid + p * 256;
            int row = c >> 3, col = c & 7;
            int m = mBase + row;
            int b2 = m >> 11, t = m & 2047;
            const char* ga = (const char*)g_avw +
                ((size_t)(kt * BATCH + b2) * TSEQ + t) * 128 + col * 16;
            cp16(sa + row * 144 + col * 16, ga);
            cp16(sbb + row * 144 + col * 16,
                 gB + (size_t)row * 2048 + kt * 128 + col * 16);
        }
    };

    issue(0, 0);
    CP_COMMIT();

    for (int kt = 0; kt < 16; kt++) {
        const int buf = kt & 1;
        if (kt < 15) {
            issue(kt + 1, buf ^ 1);
            CP_COMMIT();
            CP_WAIT(1);
        } else {
            CP_WAIT(0);
        }
        __syncthreads();

        const uint32_t* As = smw + buf * 4608;
        const uint32_t* Bs = smw + 9216 + buf * 4608;
#pragma unroll
        for (int kk = 0; kk < 32; kk += 8) {
            uint32_t af[2][4];
#pragma unroll
            for (int mi = 0; mi < 2; mi++) {
                const uint32_t* qb = &As[(wm * 32 + mi * 16 + gid) * GSTW];
                af[mi][0] = qb[kk + tg];
                af[mi][1] = qb[8 * GSTW + kk + tg];
                af[mi][2] = qb[kk + tg + 4];
                af[mi][3] = qb[8 * GSTW + kk + tg + 4];
            }
#pragma unroll
            for (int ni = 0; ni < 8; ni++) {
                const uint32_t* bb = &Bs[(wn * 64 + ni * 8 + gid) * GSTW];
                uint32_t b0 = bb[kk + tg];
                uint32_t b1 = bb[kk + tg + 4];
                mma_bf16(acc[0][ni], af[0], b0, b1);
                mma_bf16(acc[1][ni], af[1], b0, b1);
            }
        }
        __syncthreads();
    }

    // epilogue: residual add (fp32), write g_y
#pragma unroll
    for (int mi = 0; mi < 2; mi++) {
        int r0 = mBase + wm * 32 + mi * 16 + gid;
        int r1 = r0 + 8;
#pragma unroll
        for (int ni = 0; ni < 8; ni++) {
            int n = nBase + wn * 64 + ni * 8 + tg * 2;
            float2 i0 = *(const float2*)(inp + (size_t)r0 * DMODEL + n);
            float2 i1 = *(const float2*)(inp + (size_t)r1 * DMODEL + n);
            *(float2*)(g_y + (size_t)r0 * DMODEL + n) =
                make_float2(acc[mi][ni][0] + i0.x, acc[mi][ni][1] + i0.y);
            *(float2*)(g_y + (size_t)r1 * DMODEL + n) =
                make_float2(acc[mi][ni][2] + i1.x, acc[mi][ni][3] + i1.y);
        }
    }
}

// ===========================================================================
// Kernel 4: LayerNorm. One warp per row of 1024.
// ===========================================================================
__global__ __launch_bounds__(256) void ln_kernel(
    const float* __restrict__ gamma,
    const float* __restrict__ beta,
    float* __restrict__ out)
{
    const int row  = blockIdx.x * 8 + (threadIdx.x >> 5);
    const int lane = threadIdx.x & 31;
    const float* x = g_y + (size_t)row * DMODEL;

    float4 v[8];
    float s1 = 0.f, s2 = 0.f;
#pragma unroll
    for (int i = 0; i < 8; i++) {
        v[i] = *(const float4*)(x + lane * 4 + i * 128);
        s1 += v[i].x + v[i].y + v[i].z + v[i].w;
        s2 += v[i].x * v[i].x + v[i].y * v[i].y + v[i].z * v[i].z + v[i].w * v[i].w;
    }
#pragma unroll
    for (int off = 16; off > 0; off >>= 1) {
        s1 += __shfl_xor_sync(0xFFFFFFFFu, s1, off);
        s2 += __shfl_xor_sync(0xFFFFFFFFu, s2, off);
    }
    float mu   = s1 * (1.0f / DMODEL);
    float var  = s2 * (1.0f / DMODEL) - mu * mu;
    float rstd = rsqrtf(var + LN_EPS);

    float* o = out + (size_t)row * DMODEL;
#pragma unroll
    for (int i = 0; i < 8; i++) {
        int cbase = lane * 4 + i * 128;
        float4 g = *(const float4*)(gamma + cbase);
        float4 b = *(const float4*)(beta + cbase);
        float4 r;
        r.x = (v[i].x - mu) * rstd * g.x + b.x;
        r.y = (v[i].y - mu) * rstd * g.y + b.y;
        r.z = (v[i].z - mu) * rstd * g.z + b.z;
        r.w = (v[i].w - mu) * rstd * g.w + b.w;
        *(float4*)(o + cbase) = r;
    }
}

// ===========================================================================
extern "C" void kernel_launch(void* const* d_in, const int* in_sizes, int n_in,
                              void* d_out, int out_size)
{
    const float* inp   = (const float*)d_in[0];
    const float* Wqkv  = (const float*)d_in[1];
    const float* bqkv  = (const float*)d_in[2];
    const float* Wo    = (const float*)d_in[3];
    const float* gamma = (const float*)d_in[4];
    const float* beta  = (const float*)d_in[5];
    float* out = (float*)d_out;

    cudaFuncSetAttribute(qkv_gemm_kernel,
                         cudaFuncAttributeMaxDynamicSharedMemorySize,
                         GEMM_SMEM_BYTES);
    cudaFuncSetAttribute(oproj_kernel,
                         cudaFuncAttributeMaxDynamicSharedMemorySize,
                         GEMM_SMEM_BYTES);
    cudaFuncSetAttribute(attn_kernel,
                         cudaFuncAttributeMaxDynamicSharedMemorySize,
                         ATTN_SMEM_BYTES);

    cvt_kernel<<<CVT_TOTAL / 256, 256>>>(inp, Wqkv, Wo);
    qkv_gemm_kernel<<<dim3(N_QKV / 128, MROWS / 128), 256, GEMM_SMEM_BYTES>>>(bqkv);
    attn_kernel<<<dim3(TSEQ / 128, BH), 256, ATTN_SMEM_BYTES>>>();
    oproj_kernel<<<dim3(DMODEL / 128, MROWS / 128), 256, GEMM_SMEM_BYTES>>>(inp);
    ln_kernel<<<MROWS / 8, 256>>>(gamma, beta, out);
}

// round 10
// speedup vs baseline: 5.8434x; 1.4417x over previous
#include <cuda_runtime.h>
#include <cuda_bf16.h>
#include <cstdint>

// Problem constants
#define BATCH   2
#define TSEQ    2048
#define NHEAD   16
#define DHEAD   64
#define DMODEL  1024
#define BH      (BATCH * NHEAD)        // 32
#define MROWS   (BATCH * TSEQ)         // 4096
#define N_QKV   (3 * NHEAD * DHEAD)    // 3072
#define ATTN_SCALE 0.125f              // 1/sqrt(64)
#define LN_EPS  1e-5f

// ---------------- scratch (static device globals; no allocations) ----------
__device__ __align__(16) uint32_t g_inp_bf [MROWS * DMODEL / 2];
__device__ __align__(16) uint32_t g_wqkv_bf[N_QKV * DMODEL / 2];
__device__ __align__(16) uint32_t g_wo_bf  [DMODEL * DMODEL / 2];
__device__ __align__(16) uint32_t g_qw [BH * TSEQ * 32];  // [bh][t][d/2]
__device__ __align__(16) uint32_t g_kw [BH * TSEQ * 32];
__device__ __align__(16) uint32_t g_vw [BH * TSEQ * 32];
__device__ __align__(16) uint32_t g_avw[BH * TSEQ * 32];  // attn out, L=b*16+h
__device__ float g_y[MROWS * DMODEL];                     // pre-LN fp32

// ---------------- helpers --------------------------------------------------
__device__ __forceinline__ uint32_t pack_bf16(float lo, float hi) {
    __nv_bfloat162 h = __floats2bfloat162_rn(lo, hi);
    return *reinterpret_cast<uint32_t*>(&h);
}

__device__ __forceinline__ uint32_t smem_u32(const void* p) {
    uint32_t a;
    asm("{ .reg .u64 t; cvta.to.shared.u64 t, %1; cvt.u32.u64 %0, t; }"
        : "=r"(a) : "l"(p));
    return a;
}

__device__ __forceinline__ void cp16(uint32_t s, const void* g) {
    asm volatile("cp.async.cg.shared.global [%0], [%1], 16;"
                 :: "r"(s), "l"(g) : "memory");
}
#define CP_COMMIT() asm volatile("cp.async.commit_group;" ::: "memory")
#define CP_WAIT(n)  asm volatile("cp.async.wait_group %0;" :: "n"(n) : "memory")

// mma.sync m16n8k16 bf16 (fp32 accum).
// A frag: a0=[row gid][kword tg] a1=[gid+8][tg] a2=[gid][tg+4] a3=[gid+8][tg+4]
// B frag: b0=[n gid][kword tg] b1=[gid][tg+4]
// C frag: c0=(gid,2tg) c1=(gid,2tg+1) c2=(gid+8,2tg) c3=(gid+8,2tg+1)
__device__ __forceinline__ void mma_bf16(float* c, const uint32_t* a,
                                         uint32_t b0, uint32_t b1) {
    asm volatile(
        "mma.sync.aligned.m16n8k16.row.col.f32.bf16.bf16.f32 "
        "{%0,%1,%2,%3}, {%4,%5,%6,%7}, {%8,%9}, {%0,%1,%2,%3};"
        : "+f"(c[0]), "+f"(c[1]), "+f"(c[2]), "+f"(c[3])
        : "r"(a[0]), "r"(a[1]), "r"(a[2]), "r"(a[3]), "r"(b0), "r"(b1));
}

#define GSTW 36   // smem row stride in words (36 % 32 == 4 -> conflict-free)

// ===========================================================================
// Kernel 0: one-time fp32 -> bf16 pre-convert of inp / W_qkv / W_o.
// ===========================================================================
#define CVT_T1 (MROWS * DMODEL / 4)
#define CVT_T2 (N_QKV * DMODEL / 4)
#define CVT_T3 (DMODEL * DMODEL / 4)
#define CVT_TOTAL (CVT_T1 + CVT_T2 + CVT_T3)

__global__ __launch_bounds__(256) void cvt_kernel(
    const float* __restrict__ inp,
    const float* __restrict__ wqkv,
    const float* __restrict__ wo)
{
    int idx = blockIdx.x * 256 + threadIdx.x;
    const float4* src;
    uint2* dst;
    int li;
    if (idx < CVT_T1) {
        src = (const float4*)inp;  dst = (uint2*)g_inp_bf;  li = idx;
    } else if (idx < CVT_T1 + CVT_T2) {
        src = (const float4*)wqkv; dst = (uint2*)g_wqkv_bf; li = idx - CVT_T1;
    } else {
        src = (const float4*)wo;   dst = (uint2*)g_wo_bf;   li = idx - CVT_T1 - CVT_T2;
    }
    float4 v = src[li];
    dst[li] = make_uint2(pack_bf16(v.x, v.y), pack_bf16(v.z, v.w));
}

// ===========================================================================
// Kernel 1: QKV GEMM, bf16 mma + cp.async double-buffered pipeline (as R7).
// ===========================================================================
#define GEMM_SMEM_BYTES 73728

__device__ __forceinline__ void gemm_issue_tile(
    uint32_t sbase, const char* gA, const char* gB, int kt, int buf, int tid)
{
    const uint32_t sa  = sbase + buf * 18432;
    const uint32_t sbb = sbase + 36864 + buf * 18432;
#pragma unroll
    for (int p = 0; p < 4; p++) {
        int c = tid + p * 256;
        int row = c >> 3, col = c & 7;
        cp16(sa  + row * 144 + col * 16, gA + (size_t)row * 2048 + kt * 128 + col * 16);
        cp16(sbb + row * 144 + col * 16, gB + (size_t)row * 2048 + kt * 128 + col * 16);
    }
}

__global__ __launch_bounds__(256) void qkv_gemm_kernel(
    const float* __restrict__ bias)
{
    extern __shared__ __align__(16) uint32_t smw[];
    const uint32_t sb = smem_u32(smw);

    const int tid  = threadIdx.x;
    const int lane = tid & 31;
    const int warp = tid >> 5;
    const int gid  = lane >> 2;
    const int tg   = lane & 3;
    const int wm   = warp & 3;
    const int wn   = warp >> 2;
    const int mBase = blockIdx.y * 128;
    const int nBase = blockIdx.x * 128;

    const char* gA = (const char*)g_inp_bf  + (size_t)mBase * 2048;
    const char* gB = (const char*)g_wqkv_bf + (size_t)nBase * 2048;

    float acc[2][8][4];
#pragma unroll
    for (int mi = 0; mi < 2; mi++)
#pragma unroll
        for (int ni = 0; ni < 8; ni++)
#pragma unroll
            for (int j = 0; j < 4; j++) acc[mi][ni][j] = 0.f;

    gemm_issue_tile(sb, gA, gB, 0, 0, tid);
    CP_COMMIT();

    for (int kt = 0; kt < 16; kt++) {
        const int buf = kt & 1;
        if (kt < 15) {
            gemm_issue_tile(sb, gA, gB, kt + 1, buf ^ 1, tid);
            CP_COMMIT();
            CP_WAIT(1);
        } else {
            CP_WAIT(0);
        }
        __syncthreads();

        const uint32_t* As = smw + buf * 4608;
        const uint32_t* Bs = smw + 9216 + buf * 4608;
#pragma unroll
        for (int kk = 0; kk < 32; kk += 8) {
            uint32_t af[2][4];
#pragma unroll
            for (int mi = 0; mi < 2; mi++) {
                const uint32_t* qb = &As[(wm * 32 + mi * 16 + gid) * GSTW];
                af[mi][0] = qb[kk + tg];
                af[mi][1] = qb[8 * GSTW + kk + tg];
                af[mi][2] = qb[kk + tg + 4];
                af[mi][3] = qb[8 * GSTW + kk + tg + 4];
            }
#pragma unroll
            for (int ni = 0; ni < 8; ni++) {
                const uint32_t* bb = &Bs[(wn * 64 + ni * 8 + gid) * GSTW];
                uint32_t b0 = bb[kk + tg];
                uint32_t b1 = bb[kk + tg + 4];
                mma_bf16(acc[0][ni], af[0], b0, b1);
                mma_bf16(acc[1][ni], af[1], b0, b1);
            }
        }
        __syncthreads();
    }

#pragma unroll
    for (int mi = 0; mi < 2; mi++) {
        int r0 = mBase + wm * 32 + mi * 16 + gid;
        int r1 = r0 + 8;
        int bb0 = r0 >> 11, t0 = r0 & 2047;
        int bb1 = r1 >> 11, t1 = r1 & 2047;
#pragma unroll
        for (int ni = 0; ni < 8; ni++) {
            int n = nBase + wn * 64 + ni * 8 + tg * 2;
            int third = n >> 10;
            int nn = n & 1023;
            int h = nn >> 6, d = nn & 63;
            uint32_t* base = (third == 0) ? g_qw : ((third == 1) ? g_kw : g_vw);
            float2 bi = *(const float2*)(bias + n);
            base[((bb0 * NHEAD + h) * TSEQ + t0) * 32 + d / 2] =
                pack_bf16(acc[mi][ni][0] + bi.x, acc[mi][ni][1] + bi.y);
            base[((bb1 * NHEAD + h) * TSEQ + t1) * 32 + d / 2] =
                pack_bf16(acc[mi][ni][2] + bi.x, acc[mi][ni][3] + bi.y);
        }
    }
}

// ===========================================================================
// Kernel 2: flash attention, FA2-style register softmax.
// CTA: (bh, 128-row q-block), 256 thr = 8 warps; warp owns 16 rows x 64 keys.
// Q lives in register A-fragments (loaded once). S/P never touch smem.
// K double-buffered via cp.async; V prefetched to regs, byte_perm-transposed
// into double-buffered Vt. ONE __syncthreads per key-tile.
// Smem (words): Qb[128][36] | Kb[2][64][36] | Vt[2][64][36]
// ===========================================================================
#define QB_OFF  0
#define KB_OFF  (128 * GSTW)                    // 4608
#define VT_OFF  (KB_OFF + 2 * 64 * GSTW)        // 9216
#define ATTN_SMEM_WORDS (VT_OFF + 2 * 64 * GSTW)
#define ATTN_SMEM_BYTES (ATTN_SMEM_WORDS * 4)   // 55296

__global__ __launch_bounds__(256) void attn_kernel()
{
    extern __shared__ __align__(16) uint32_t smw[];
    const uint32_t sb = smem_u32(smw);

    const int tid  = threadIdx.x;
    const int lane = tid & 31;
    const int warp = tid >> 5;
    const int gid  = lane >> 2;
    const int tg   = lane & 3;
    const int bh   = blockIdx.y;
    const int q0   = blockIdx.x * 128;

    // per-thread V prefetch slice (fixed for all tiles)
    const int vkp = tid & 31;          // key-pair index 0..31
    const int vdb = (tid >> 5) * 8;    // 8 d values

    // ---- stage Q tile into smem (coalesced), then lift to register frags --
    {
        const int qr = tid >> 1;
        const int hb = (tid & 1) * 16;
        const uint32_t* gq = g_qw + (size_t)(bh * TSEQ + q0 + qr) * 32 + hb;
        uint32_t* qrow = &smw[QB_OFF + qr * GSTW + hb];
#pragma unroll
        for (int i = 0; i < 4; i++)
            *(uint4*)&qrow[i * 4] = *(const uint4*)(gq + i * 4);
    }
    // ---- prologue: K0 via cp.async, V0 direct loads ----
    {
        const char* gk = (const char*)g_kw + (size_t)(bh * TSEQ) * 128;
        const uint32_t kbb = sb + KB_OFF * 4;
#pragma unroll
        for (int p = 0; p < 2; p++) {
            int c = tid + p * 256;
            int row = c >> 3, col = c & 7;
            cp16(kbb + row * 144 + col * 16, gk + row * 128 + col * 16);
        }
        CP_COMMIT();
    }
    uint4 va, vb;
    {
        const uint32_t* gv0 = g_vw + (size_t)(bh * TSEQ + 2 * vkp) * 32 + vdb / 2;
        va = *(const uint4*)gv0;
        vb = *(const uint4*)(gv0 + 32);
    }
    CP_WAIT(0);
    __syncthreads();          // Q + K0 visible

    // Q register fragments: rows warp*16+gid(+8), 4 k16 groups
    uint32_t qf[4][4];
    {
        const uint32_t* q0p = &smw[QB_OFF + (warp * 16 + gid) * GSTW];
#pragma unroll
        for (int j = 0; j < 4; j++) {
            qf[j][0] = q0p[j * 8 + tg];
            qf[j][1] = q0p[8 * GSTW + j * 8 + tg];
            qf[j][2] = q0p[j * 8 + tg + 4];
            qf[j][3] = q0p[8 * GSTW + j * 8 + tg + 4];
        }
    }
    // write V0 transpose into Vt buf0
    {
        uint32_t* vt = &smw[VT_OFF + vdb * GSTW + vkp];
        vt[0 * GSTW] = __byte_perm(va.x, vb.x, 0x5410);
        vt[1 * GSTW] = __byte_perm(va.x, vb.x, 0x7632);
        vt[2 * GSTW] = __byte_perm(va.y, vb.y, 0x5410);
        vt[3 * GSTW] = __byte_perm(va.y, vb.y, 0x7632);
        vt[4 * GSTW] = __byte_perm(va.z, vb.z, 0x5410);
        vt[5 * GSTW] = __byte_perm(va.z, vb.z, 0x7632);
        vt[6 * GSTW] = __byte_perm(va.w, vb.w, 0x5410);
        vt[7 * GSTW] = __byte_perm(va.w, vb.w, 0x7632);
    }
    __syncthreads();          // Vt0 visible

    float oacc[8][4];
#pragma unroll
    for (int ni = 0; ni < 8; ni++)
#pragma unroll
        for (int j = 0; j < 4; j++) oacc[ni][j] = 0.f;
    float m0 = -1e30f, m1 = -1e30f, l0 = 0.f, l1 = 0.f;

    for (int kt = 0; kt < TSEQ / 64; kt++) {
        const int buf = kt & 1;
        const int nbuf = buf ^ 1;

        // prefetch next tile: K via cp.async, V into registers
        if (kt < TSEQ / 64 - 1) {
            const char* gk = (const char*)g_kw +
                (size_t)(bh * TSEQ + (kt + 1) * 64) * 128;
            const uint32_t kbb = sb + (KB_OFF + nbuf * 64 * GSTW) * 4;
#pragma unroll
            for (int p = 0; p < 2; p++) {
                int c = tid + p * 256;
                int row = c >> 3, col = c & 7;
                cp16(kbb + row * 144 + col * 16, gk + row * 128 + col * 16);
            }
            CP_COMMIT();
            const uint32_t* gv0 = g_vw +
                (size_t)(bh * TSEQ + (kt + 1) * 64 + 2 * vkp) * 32 + vdb / 2;
            va = *(const uint4*)gv0;
            vb = *(const uint4*)(gv0 + 32);
        }

        // ---- GEMM1: s[128(own 16),64] = Q·K^T, all in regs ----
        float s[8][4];
#pragma unroll
        for (int ni = 0; ni < 8; ni++)
#pragma unroll
            for (int j = 0; j < 4; j++) s[ni][j] = 0.f;
        const uint32_t* kb = &smw[KB_OFF + buf * 64 * GSTW];
#pragma unroll
        for (int j = 0; j < 4; j++) {
#pragma unroll
            for (int ni = 0; ni < 8; ni++) {
                const uint32_t* kr = &kb[(ni * 8 + gid) * GSTW];
                mma_bf16(s[ni], qf[j], kr[j * 8 + tg], kr[j * 8 + tg + 4]);
            }
        }

        // ---- register softmax (rows gid / gid+8, quad shfl reduce) ----
        float mx0 = -1e30f, mx1 = -1e30f;
#pragma unroll
        for (int ni = 0; ni < 8; ni++) {
            s[ni][0] *= ATTN_SCALE; s[ni][1] *= ATTN_SCALE;
            s[ni][2] *= ATTN_SCALE; s[ni][3] *= ATTN_SCALE;
            mx0 = fmaxf(mx0, fmaxf(s[ni][0], s[ni][1]));
            mx1 = fmaxf(mx1, fmaxf(s[ni][2], s[ni][3]));
        }
        mx0 = fmaxf(mx0, __shfl_xor_sync(0xFFFFFFFFu, mx0, 1));
        mx0 = fmaxf(mx0, __shfl_xor_sync(0xFFFFFFFFu, mx0, 2));
        mx1 = fmaxf(mx1, __shfl_xor_sync(0xFFFFFFFFu, mx1, 1));
        mx1 = fmaxf(mx1, __shfl_xor_sync(0xFFFFFFFFu, mx1, 2));
        const float nm0 = fmaxf(m0, mx0), nm1 = fmaxf(m1, mx1);
        const float cr0 = __expf(m0 - nm0), cr1 = __expf(m1 - nm1);
        m0 = nm0; m1 = nm1;

        float sum0 = 0.f, sum1 = 0.f;
#pragma unroll
        for (int ni = 0; ni < 8; ni++) {
            s[ni][0] = __expf(s[ni][0] - nm0);
            s[ni][1] = __expf(s[ni][1] - nm0);
            s[ni][2] = __expf(s[ni][2] - nm1);
            s[ni][3] = __expf(s[ni][3] - nm1);
            sum0 += s[ni][0] + s[ni][1];
            sum1 += s[ni][2] + s[ni][3];
        }
        sum0 += __shfl_xor_sync(0xFFFFFFFFu, sum0, 1);
        sum0 += __shfl_xor_sync(0xFFFFFFFFu, sum0, 2);
        sum1 += __shfl_xor_sync(0xFFFFFFFFu, sum1, 1);
        sum1 += __shfl_xor_sync(0xFFFFFFFFu, sum1, 2);
        l0 = l0 * cr0 + sum0;
        l1 = l1 * cr1 + sum1;

        // P register A-fragments: C(ni=2j)->a0/a1, C(ni=2j+1)->a2/a3
        uint32_t pf[4][4];
#pragma unroll
        for (int j = 0; j < 4; j++) {
            pf[j][0] = pack_bf16(s[2 * j][0],     s[2 * j][1]);
            pf[j][1] = pack_bf16(s[2 * j][2],     s[2 * j][3]);
            pf[j][2] = pack_bf16(s[2 * j + 1][0], s[2 * j + 1][1]);
            pf[j][3] = pack_bf16(s[2 * j + 1][2], s[2 * j + 1][3]);
        }

        // rescale O accumulators
#pragma unroll
        for (int ni = 0; ni < 8; ni++) {
            oacc[ni][0] *= cr0; oacc[ni][1] *= cr0;
            oacc[ni][2] *= cr1; oacc[ni][3] *= cr1;
        }

        // ---- GEMM2: O += P·V  (B frags from Vt[d][keypair]) ----
        const uint32_t* vtb = &smw[VT_OFF + buf * 64 * GSTW];
#pragma unroll
        for (int j = 0; j < 4; j++) {
#pragma unroll
            for (int ni = 0; ni < 8; ni++) {
                const uint32_t* vr = &vtb[(ni * 8 + gid) * GSTW];
                mma_bf16(oacc[ni], pf[j], vr[j * 8 + tg], vr[j * 8 + tg + 4]);
            }
        }

        // rotate buffers: write prefetched V, wait K copy, one sync
        if (kt < TSEQ / 64 - 1) {
            uint32_t* vt = &smw[VT_OFF + nbuf * 64 * GSTW + vdb * GSTW + vkp];
            vt[0 * GSTW] = __byte_perm(va.x, vb.x, 0x5410);
            vt[1 * GSTW] = __byte_perm(va.x, vb.x, 0x7632);
            vt[2 * GSTW] = __byte_perm(va.y, vb.y, 0x5410);
            vt[3 * GSTW] = __byte_perm(va.y, vb.y, 0x7632);
            vt[4 * GSTW] = __byte_perm(va.z, vb.z, 0x5410);
            vt[5 * GSTW] = __byte_perm(va.z, vb.z, 0x7632);
            vt[6 * GSTW] = __byte_perm(va.w, vb.w, 0x5410);
            vt[7 * GSTW] = __byte_perm(va.w, vb.w, 0x7632);
            CP_WAIT(0);
        }
        __syncthreads();
    }

    // ---- writeback normalized bf16 output ----
    const float il0 = 1.0f / l0, il1 = 1.0f / l1;
    const int r0 = q0 + warp * 16 + gid;
    const int r1 = r0 + 8;
#pragma unroll
    for (int ni = 0; ni < 8; ni++) {
        int cw = (ni * 8 + tg * 2) / 2;
        g_avw[(size_t)(bh * TSEQ + r0) * 32 + cw] =
            pack_bf16(oacc[ni][0] * il0, oacc[ni][1] * il0);
        g_avw[(size_t)(bh * TSEQ + r1) * 32 + cw] =
            pack_bf16(oacc[ni][2] * il1, oacc[ni][3] * il1);
    }
}

// ===========================================================================
// Kernel 3: O-projection + residual, bf16 mma + cp.async pipeline (as R7).
// ===========================================================================
__global__ __launch_bounds__(256) void oproj_kernel(
    const float* __restrict__ inp)
{
    extern __shared__ __align__(16) uint32_t smw[];
    const uint32_t sb = smem_u32(smw);

    const int tid  = threadIdx.x;
    const int lane = tid & 31;
    const int warp = tid >> 5;
    const int gid  = lane >> 2;
    const int tg   = lane & 3;
    const int wm   = warp & 3;
    const int wn   = warp >> 2;
    const int mBase = blockIdx.y * 128;
    const int nBase = blockIdx.x * 128;

    const char* gB = (const char*)g_wo_bf + (size_t)nBase * 2048;

    float acc[2][8][4];
#pragma unroll
    for (int mi = 0; mi < 2; mi++)
#pragma unroll
        for (int ni = 0; ni < 8; ni++)
#pragma unroll
            for (int j = 0; j < 4; j++) acc[mi][ni][j] = 0.f;

    auto issue = [&](int kt, int buf) {
        const uint32_t sa  = sb + buf * 18432;
        const uint32_t sbb = sb + 36864 + buf * 18432;
#pragma unroll
        for (int p = 0; p < 4; p++) {
            int c = tid + p * 256;
            int row = c >> 3, col = c & 7;
            int m = mBase + row;
            int b2 = m >> 11, t = m & 2047;
            const char* ga = (const char*)g_avw +
                ((size_t)(kt * BATCH + b2) * TSEQ + t) * 128 + col * 16;
            cp16(sa + row * 144 + col * 16, ga);
            cp16(sbb + row * 144 + col * 16,
                 gB + (size_t)row * 2048 + kt * 128 + col * 16);
        }
    };

    issue(0, 0);
    CP_COMMIT();

    for (int kt = 0; kt < 16; kt++) {
        const int buf = kt & 1;
        if (kt < 15) {
            issue(kt + 1, buf ^ 1);
            CP_COMMIT();
            CP_WAIT(1);
        } else {
            CP_WAIT(0);
        }
        __syncthreads();

        const uint32_t* As = smw + buf * 4608;
        const uint32_t* Bs = smw + 9216 + buf * 4608;
#pragma unroll
        for (int kk = 0; kk < 32; kk += 8) {
            uint32_t af[2][4];
#pragma unroll
            for (int mi = 0; mi < 2; mi++) {
                const uint32_t* qb = &As[(wm * 32 + mi * 16 + gid) * GSTW];
                af[mi][0] = qb[kk + tg];
                af[mi][1] = qb[8 * GSTW + kk + tg];
                af[mi][2] = qb[kk + tg + 4];
                af[mi][3] = qb[8 * GSTW + kk + tg + 4];
            }
#pragma unroll
            for (int ni = 0; ni < 8; ni++) {
                const uint32_t* bb = &Bs[(wn * 64 + ni * 8 + gid) * GSTW];
                uint32_t b0 = bb[kk + tg];
                uint32_t b1 = bb[kk + tg + 4];
                mma_bf16(acc[0][ni], af[0], b0, b1);
                mma_bf16(acc[1][ni], af[1], b0, b1);
            }
        }
        __syncthreads();
    }

#pragma unroll
    for (int mi = 0; mi < 2; mi++) {
        int r0 = mBase + wm * 32 + mi * 16 + gid;
        int r1 = r0 + 8;
#pragma unroll
        for (int ni = 0; ni < 8; ni++) {
            int n = nBase + wn * 64 + ni * 8 + tg * 2;
            float2 i0 = *(const float2*)(inp + (size_t)r0 * DMODEL + n);
            float2 i1 = *(const float2*)(inp + (size_t)r1 * DMODEL + n);
            *(float2*)(g_y + (size_t)r0 * DMODEL + n) =
                make_float2(acc[mi][ni][0] + i0.x, acc[mi][ni][1] + i0.y);
            *(float2*)(g_y + (size_t)r1 * DMODEL + n) =
                make_float2(acc[mi][ni][2] + i1.x, acc[mi][ni][3] + i1.y);
        }
    }
}

// ===========================================================================
// Kernel 4: LayerNorm. One warp per row of 1024.
// ===========================================================================
__global__ __launch_bounds__(256) void ln_kernel(
    const float* __restrict__ gamma,
    const float* __restrict__ beta,
    float* __restrict__ out)
{
    const int row  = blockIdx.x * 8 + (threadIdx.x >> 5);
    const int lane = threadIdx.x & 31;
    const float* x = g_y + (size_t)row * DMODEL;

    float4 v[8];
    float s1 = 0.f, s2 = 0.f;
#pragma unroll
    for (int i = 0; i < 8; i++) {
        v[i] = *(const float4*)(x + lane * 4 + i * 128);
        s1 += v[i].x + v[i].y + v[i].z + v[i].w;
        s2 += v[i].x * v[i].x + v[i].y * v[i].y + v[i].z * v[i].z + v[i].w * v[i].w;
    }
#pragma unroll
    for (int off = 16; off > 0; off >>= 1) {
        s1 += __shfl_xor_sync(0xFFFFFFFFu, s1, off);
        s2 += __shfl_xor_sync(0xFFFFFFFFu, s2, off);
    }
    float mu   = s1 * (1.0f / DMODEL);
    float var  = s2 * (1.0f / DMODEL) - mu * mu;
    float rstd = rsqrtf(var + LN_EPS);

    float* o = out + (size_t)row * DMODEL;
#pragma unroll
    for (int i = 0; i < 8; i++) {
        int cbase = lane * 4 + i * 128;
        float4 g = *(const float4*)(gamma + cbase);
        float4 b = *(const float4*)(beta + cbase);
        float4 r;
        r.x = (v[i].x - mu) * rstd * g.x + b.x;
        r.y = (v[i].y - mu) * rstd * g.y + b.y;
        r.z = (v[i].z - mu) * rstd * g.z + b.z;
        r.w = (v[i].w - mu) * rstd * g.w + b.w;
        *(float4*)(o + cbase) = r;
    }
}

// ===========================================================================
extern "C" void kernel_launch(void* const* d_in, const int* in_sizes, int n_in,
                              void* d_out, int out_size)
{
    const float* inp   = (const float*)d_in[0];
    const float* Wqkv  = (const float*)d_in[1];
    const float* bqkv  = (const float*)d_in[2];
    const float* Wo    = (const float*)d_in[3];
    const float* gamma = (const float*)d_in[4];
    const float* beta  = (const float*)d_in[5];
    float* out = (float*)d_out;

    cudaFuncSetAttribute(qkv_gemm_kernel,
                         cudaFuncAttributeMaxDynamicSharedMemorySize,
                         GEMM_SMEM_BYTES);
    cudaFuncSetAttribute(oproj_kernel,
                         cudaFuncAttributeMaxDynamicSharedMemorySize,
                         GEMM_SMEM_BYTES);
    cudaFuncSetAttribute(attn_kernel,
                         cudaFuncAttributeMaxDynamicSharedMemorySize,
                         ATTN_SMEM_BYTES);

    cvt_kernel<<<CVT_TOTAL / 256, 256>>>(inp, Wqkv, Wo);
    qkv_gemm_kernel<<<dim3(N_QKV / 128, MROWS / 128), 256, GEMM_SMEM_BYTES>>>(bqkv);
    attn_kernel<<<dim3(TSEQ / 128, BH), 256, ATTN_SMEM_BYTES>>>();
    oproj_kernel<<<dim3(DMODEL / 128, MROWS / 128), 256, GEMM_SMEM_BYTES>>>(inp);
    ln_kernel<<<MROWS / 8, 256>>>(gamma, beta, out);
}

// round 11
// speedup vs baseline: 6.2807x; 1.0748x over previous
#include <cuda_runtime.h>
#include <cuda_bf16.h>
#include <cstdint>

// Problem constants
#define BATCH   2
#define TSEQ    2048
#define NHEAD   16
#define DHEAD   64
#define DMODEL  1024
#define BH      (BATCH * NHEAD)        // 32
#define MROWS   (BATCH * TSEQ)         // 4096
#define N_QKV   (3 * NHEAD * DHEAD)    // 3072
#define ATTN_SCALE 0.125f              // 1/sqrt(64)
#define LN_EPS  1e-5f

// ---------------- scratch (static device globals; no allocations) ----------
__device__ __align__(16) uint32_t g_inp_bf [MROWS * DMODEL / 2];
__device__ __align__(16) uint32_t g_wqkv_bf[N_QKV * DMODEL / 2];
__device__ __align__(16) uint32_t g_wo_bf  [DMODEL * DMODEL / 2];
__device__ __align__(16) uint32_t g_qw [BH * TSEQ * 32];  // [bh][t][d/2]
__device__ __align__(16) uint32_t g_kw [BH * TSEQ * 32];
__device__ __align__(16) uint32_t g_vw [BH * TSEQ * 32];
__device__ __align__(16) uint32_t g_avw[BH * TSEQ * 32];  // attn out, L=b*16+h
__device__ float g_y[MROWS * DMODEL];                     // pre-LN fp32

// ---------------- helpers --------------------------------------------------
__device__ __forceinline__ uint32_t pack_bf16(float lo, float hi) {
    __nv_bfloat162 h = __floats2bfloat162_rn(lo, hi);
    return *reinterpret_cast<uint32_t*>(&h);
}

__device__ __forceinline__ uint32_t smem_u32(const void* p) {
    uint32_t a;
    asm("{ .reg .u64 t; cvta.to.shared.u64 t, %1; cvt.u32.u64 %0, t; }"
        : "=r"(a) : "l"(p));
    return a;
}

__device__ __forceinline__ void cp16(uint32_t s, const void* g) {
    asm volatile("cp.async.cg.shared.global [%0], [%1], 16;"
                 :: "r"(s), "l"(g) : "memory");
}
#define CP_COMMIT() asm volatile("cp.async.commit_group;" ::: "memory")
#define CP_WAIT(n)  asm volatile("cp.async.wait_group %0;" :: "n"(n) : "memory")

// ldmatrix x4: 4 8x8 b16 matrices; lane groups 0-7/8-15/16-23/24-31 give the
// row addresses of matrices 0..3 -> regs r0..r3.
__device__ __forceinline__ void ldm_x4(uint32_t* r, uint32_t a) {
    asm volatile("ldmatrix.sync.aligned.m8n8.x4.shared.b16 {%0,%1,%2,%3}, [%4];"
                 : "=r"(r[0]), "=r"(r[1]), "=r"(r[2]), "=r"(r[3]) : "r"(a));
}
__device__ __forceinline__ void ldm_x4_t(uint32_t* r, uint32_t a) {
    asm volatile("ldmatrix.sync.aligned.m8n8.x4.trans.shared.b16 {%0,%1,%2,%3}, [%4];"
                 : "=r"(r[0]), "=r"(r[1]), "=r"(r[2]), "=r"(r[3]) : "r"(a));
}

// mma.sync m16n8k16 bf16 (fp32 accum).
__device__ __forceinline__ void mma_bf16(float* c, const uint32_t* a,
                                         uint32_t b0, uint32_t b1) {
    asm volatile(
        "mma.sync.aligned.m16n8k16.row.col.f32.bf16.bf16.f32 "
        "{%0,%1,%2,%3}, {%4,%5,%6,%7}, {%8,%9}, {%0,%1,%2,%3};"
        : "+f"(c[0]), "+f"(c[1]), "+f"(c[2]), "+f"(c[3])
        : "r"(a[0]), "r"(a[1]), "r"(a[2]), "r"(a[3]), "r"(b0), "r"(b1));
}

#define GSTW 36   // smem row stride in words (4 mod 32 -> conflict-free)
#define ROWB (GSTW * 4)   // 144 bytes

// ===========================================================================
// Kernel 0: one-time fp32 -> bf16 pre-convert of inp / W_qkv / W_o.
// ===========================================================================
#define CVT_T1 (MROWS * DMODEL / 4)
#define CVT_T2 (N_QKV * DMODEL / 4)
#define CVT_T3 (DMODEL * DMODEL / 4)
#define CVT_TOTAL (CVT_T1 + CVT_T2 + CVT_T3)

__global__ __launch_bounds__(256) void cvt_kernel(
    const float* __restrict__ inp,
    const float* __restrict__ wqkv,
    const float* __restrict__ wo)
{
    int idx = blockIdx.x * 256 + threadIdx.x;
    const float4* src;
    uint2* dst;
    int li;
    if (idx < CVT_T1) {
        src = (const float4*)inp;  dst = (uint2*)g_inp_bf;  li = idx;
    } else if (idx < CVT_T1 + CVT_T2) {
        src = (const float4*)wqkv; dst = (uint2*)g_wqkv_bf; li = idx - CVT_T1;
    } else {
        src = (const float4*)wo;   dst = (uint2*)g_wo_bf;   li = idx - CVT_T1 - CVT_T2;
    }
    float4 v = src[li];
    dst[li] = make_uint2(pack_bf16(v.x, v.y), pack_bf16(v.z, v.w));
}

// ===========================================================================
// Kernel 1: QKV GEMM, bf16 mma + cp.async double buffer + ldmatrix frags.
// Block 128x128, 8 warps (4m x 2n), warp tile 32x64, k-chunk 64 bf16.
// Smem words: A0@0 A1@4608 B0@9216 B1@13824.
// ===========================================================================
#define GEMM_SMEM_BYTES 73728

__device__ __forceinline__ void gemm_issue_tile(
    uint32_t sbase, const char* gA, const char* gB, int kt, int buf, int tid)
{
    const uint32_t sa  = sbase + buf * 18432;
    const uint32_t sbb = sbase + 36864 + buf * 18432;
#pragma unroll
    for (int p = 0; p < 4; p++) {
        int c = tid + p * 256;
        int row = c >> 3, col = c & 7;
        cp16(sa  + row * ROWB + col * 16, gA + (size_t)row * 2048 + kt * 128 + col * 16);
        cp16(sbb + row * ROWB + col * 16, gB + (size_t)row * 2048 + kt * 128 + col * 16);
    }
}

__global__ __launch_bounds__(256) void qkv_gemm_kernel(
    const float* __restrict__ bias)
{
    extern __shared__ __align__(16) uint32_t smw[];
    const uint32_t sb = smem_u32(smw);

    const int tid  = threadIdx.x;
    const int lane = tid & 31;
    const int warp = tid >> 5;
    const int gid  = lane >> 2;
    const int tg   = lane & 3;
    const int wm   = warp & 3;
    const int wn   = warp >> 2;
    const int mBase = blockIdx.y * 128;
    const int nBase = blockIdx.x * 128;

    const int lr  = lane & 15;          // ldmatrix row within 16
    const int lko = (lane >> 4) * 4;    // ldmatrix kword offset

    const char* gA = (const char*)g_inp_bf  + (size_t)mBase * 2048;
    const char* gB = (const char*)g_wqkv_bf + (size_t)nBase * 2048;

    float acc[2][8][4];
#pragma unroll
    for (int mi = 0; mi < 2; mi++)
#pragma unroll
        for (int ni = 0; ni < 8; ni++)
#pragma unroll
            for (int j = 0; j < 4; j++) acc[mi][ni][j] = 0.f;

    gemm_issue_tile(sb, gA, gB, 0, 0, tid);
    CP_COMMIT();

    for (int kt = 0; kt < 16; kt++) {
        const int buf = kt & 1;
        if (kt < 15) {
            gemm_issue_tile(sb, gA, gB, kt + 1, buf ^ 1, tid);
            CP_COMMIT();
            CP_WAIT(1);
        } else {
            CP_WAIT(0);
        }
        __syncthreads();

        const uint32_t abase = sb + (buf * 4608) * 4;
        const uint32_t bbase = sb + (9216 + buf * 4608) * 4;
#pragma unroll
        for (int kk = 0; kk < 32; kk += 8) {
            uint32_t af[2][4];
#pragma unroll
            for (int mi = 0; mi < 2; mi++)
                ldm_x4(af[mi], abase +
                       ((wm * 32 + mi * 16 + lr) * GSTW + kk + lko) * 4);
#pragma unroll
            for (int p = 0; p < 4; p++) {
                uint32_t bf[4];
                ldm_x4(bf, bbase +
                       ((wn * 64 + p * 16 + lr) * GSTW + kk + lko) * 4);
                mma_bf16(acc[0][2 * p],     af[0], bf[0], bf[2]);
                mma_bf16(acc[0][2 * p + 1], af[0], bf[1], bf[3]);
                mma_bf16(acc[1][2 * p],     af[1], bf[0], bf[2]);
                mma_bf16(acc[1][2 * p + 1], af[1], bf[1], bf[3]);
            }
        }
        __syncthreads();
    }

#pragma unroll
    for (int mi = 0; mi < 2; mi++) {
        int r0 = mBase + wm * 32 + mi * 16 + gid;
        int r1 = r0 + 8;
        int bb0 = r0 >> 11, t0 = r0 & 2047;
        int bb1 = r1 >> 11, t1 = r1 & 2047;
#pragma unroll
        for (int ni = 0; ni < 8; ni++) {
            int n = nBase + wn * 64 + ni * 8 + tg * 2;
            int third = n >> 10;
            int nn = n & 1023;
            int h = nn >> 6, d = nn & 63;
            uint32_t* base = (third == 0) ? g_qw : ((third == 1) ? g_kw : g_vw);
            float2 bi = *(const float2*)(bias + n);
            base[((bb0 * NHEAD + h) * TSEQ + t0) * 32 + d / 2] =
                pack_bf16(acc[mi][ni][0] + bi.x, acc[mi][ni][1] + bi.y);
            base[((bb1 * NHEAD + h) * TSEQ + t1) * 32 + d / 2] =
                pack_bf16(acc[mi][ni][2] + bi.x, acc[mi][ni][3] + bi.y);
        }
    }
}

// ===========================================================================
// Kernel 2: flash attention, register softmax + ldmatrix frags.
// CTA (bh, 128 q-rows); 8 warps, each owns 16 rows x all 64 keys.
// K and V both [key][d] in smem, cp.async double-buffered together.
// K frags: ldmatrix;  V frags: ldmatrix.trans (no explicit transpose).
// Smem words: Qb[128][36]@0 | Kb[2][64][36]@4608 | Vs[2][64][36]@9216.
// ===========================================================================
#define QB_OFF  0
#define KB_OFF  (128 * GSTW)                     // 4608
#define VS_OFF  (KB_OFF + 2 * 64 * GSTW)         // 9216
#define ATTN_SMEM_WORDS (VS_OFF + 2 * 64 * GSTW) // 13824
#define ATTN_SMEM_BYTES (ATTN_SMEM_WORDS * 4)    // 55296

__global__ __launch_bounds__(256) void attn_kernel()
{
    extern __shared__ __align__(16) uint32_t smw[];
    const uint32_t sb = smem_u32(smw);

    const int tid  = threadIdx.x;
    const int lane = tid & 31;
    const int warp = tid >> 5;
    const int gid  = lane >> 2;
    const int tg   = lane & 3;
    const int bh   = blockIdx.y;
    const int q0   = blockIdx.x * 128;

    const int lr  = lane & 15;
    const int lko = (lane >> 4) * 4;

    auto kv_issue = [&](int kt, int buf) {
        const char* gk = (const char*)g_kw + (size_t)(bh * TSEQ + kt * 64) * 128;
        const char* gv = (const char*)g_vw + (size_t)(bh * TSEQ + kt * 64) * 128;
        const uint32_t kbb = sb + (KB_OFF + buf * 64 * GSTW) * 4;
        const uint32_t vbb = sb + (VS_OFF + buf * 64 * GSTW) * 4;
#pragma unroll
        for (int p = 0; p < 2; p++) {
            int c = tid + p * 256;
            int row = c >> 3, col = c & 7;
            cp16(kbb + row * ROWB + col * 16, gk + row * 128 + col * 16);
            cp16(vbb + row * ROWB + col * 16, gv + row * 128 + col * 16);
        }
    };

    // prologue: K0+V0 copies, stage Q
    kv_issue(0, 0);
    CP_COMMIT();
    {
        const int qr = tid >> 1;
        const int hb = (tid & 1) * 16;
        const uint32_t* gq = g_qw + (size_t)(bh * TSEQ + q0 + qr) * 32 + hb;
        uint32_t* qrow = &smw[QB_OFF + qr * GSTW + hb];
#pragma unroll
        for (int i = 0; i < 4; i++)
            *(uint4*)&qrow[i * 4] = *(const uint4*)(gq + i * 4);
    }
    CP_WAIT(0);
    __syncthreads();

    // Q register fragments (rows warp*16 .. +15), 4 k16 groups
    uint32_t qf[4][4];
#pragma unroll
    for (int j = 0; j < 4; j++)
        ldm_x4(qf[j], sb + (QB_OFF + (warp * 16 + lr) * GSTW + j * 8 + lko) * 4);

    float oacc[8][4];
#pragma unroll
    for (int ni = 0; ni < 8; ni++)
#pragma unroll
        for (int j = 0; j < 4; j++) oacc[ni][j] = 0.f;
    float m0 = -1e30f, m1 = -1e30f, l0 = 0.f, l1 = 0.f;

    for (int kt = 0; kt < TSEQ / 64; kt++) {
        const int buf = kt & 1;
        if (kt < TSEQ / 64 - 1) {
            kv_issue(kt + 1, buf ^ 1);
            CP_COMMIT();
        }

        // ---- GEMM1: s = Q·K^T  (K frags via ldmatrix) ----
        float s[8][4];
#pragma unroll
        for (int ni = 0; ni < 8; ni++)
#pragma unroll
            for (int j = 0; j < 4; j++) s[ni][j] = 0.f;
        const uint32_t kbase = sb + (KB_OFF + buf * 64 * GSTW) * 4;
#pragma unroll
        for (int j = 0; j < 4; j++) {
#pragma unroll
            for (int p = 0; p < 4; p++) {
                uint32_t bf[4];
                ldm_x4(bf, kbase + ((p * 16 + lr) * GSTW + j * 8 + lko) * 4);
                mma_bf16(s[2 * p],     qf[j], bf[0], bf[2]);
                mma_bf16(s[2 * p + 1], qf[j], bf[1], bf[3]);
            }
        }

        // ---- register softmax (rows gid / gid+8, quad shfl reduce) ----
        float mx0 = -1e30f, mx1 = -1e30f;
#pragma unroll
        for (int ni = 0; ni < 8; ni++) {
            s[ni][0] *= ATTN_SCALE; s[ni][1] *= ATTN_SCALE;
            s[ni][2] *= ATTN_SCALE; s[ni][3] *= ATTN_SCALE;
            mx0 = fmaxf(mx0, fmaxf(s[ni][0], s[ni][1]));
            mx1 = fmaxf(mx1, fmaxf(s[ni][2], s[ni][3]));
        }
        mx0 = fmaxf(mx0, __shfl_xor_sync(0xFFFFFFFFu, mx0, 1));
        mx0 = fmaxf(mx0, __shfl_xor_sync(0xFFFFFFFFu, mx0, 2));
        mx1 = fmaxf(mx1, __shfl_xor_sync(0xFFFFFFFFu, mx1, 1));
        mx1 = fmaxf(mx1, __shfl_xor_sync(0xFFFFFFFFu, mx1, 2));
        const float nm0 = fmaxf(m0, mx0), nm1 = fmaxf(m1, mx1);
        const float cr0 = __expf(m0 - nm0), cr1 = __expf(m1 - nm1);
        m0 = nm0; m1 = nm1;

        float sum0 = 0.f, sum1 = 0.f;
#pragma unroll
        for (int ni = 0; ni < 8; ni++) {
            s[ni][0] = __expf(s[ni][0] - nm0);
            s[ni][1] = __expf(s[ni][1] - nm0);
            s[ni][2] = __expf(s[ni][2] - nm1);
            s[ni][3] = __expf(s[ni][3] - nm1);
            sum0 += s[ni][0] + s[ni][1];
            sum1 += s[ni][2] + s[ni][3];
        }
        sum0 += __shfl_xor_sync(0xFFFFFFFFu, sum0, 1);
        sum0 += __shfl_xor_sync(0xFFFFFFFFu, sum0, 2);
        sum1 += __shfl_xor_sync(0xFFFFFFFFu, sum1, 1);
        sum1 += __shfl_xor_sync(0xFFFFFFFFu, sum1, 2);
        l0 = l0 * cr0 + sum0;
        l1 = l1 * cr1 + sum1;

        // P register A-fragments: C(ni=2j)->a0/a1, C(ni=2j+1)->a2/a3
        uint32_t pf[4][4];
#pragma unroll
        for (int j = 0; j < 4; j++) {
            pf[j][0] = pack_bf16(s[2 * j][0],     s[2 * j][1]);
            pf[j][1] = pack_bf16(s[2 * j][2],     s[2 * j][3]);
            pf[j][2] = pack_bf16(s[2 * j + 1][0], s[2 * j + 1][1]);
            pf[j][3] = pack_bf16(s[2 * j + 1][2], s[2 * j + 1][3]);
        }

#pragma unroll
        for (int ni = 0; ni < 8; ni++) {
            oacc[ni][0] *= cr0; oacc[ni][1] *= cr0;
            oacc[ni][2] *= cr1; oacc[ni][3] *= cr1;
        }

        // ---- GEMM2: O += P·V  (V frags via ldmatrix.trans on [key][d]) ----
        const uint32_t vbase = sb + (VS_OFF + buf * 64 * GSTW) * 4;
#pragma unroll
        for (int j = 0; j < 4; j++) {
#pragma unroll
            for (int p = 0; p < 4; p++) {
                uint32_t vf[4];
                // rows = keys j*16 + (lane&15); byte col = p*32 + (lane>>4)*16
                ldm_x4_t(vf, vbase + (j * 16 + lr) * ROWB + p * 32 + (lane >> 4) * 16);
                mma_bf16(oacc[2 * p],     pf[j], vf[0], vf[1]);
                mma_bf16(oacc[2 * p + 1], pf[j], vf[2], vf[3]);
            }
        }

        if (kt < TSEQ / 64 - 1) CP_WAIT(0);
        __syncthreads();
    }

    // ---- writeback normalized bf16 output ----
    const float il0 = 1.0f / l0, il1 = 1.0f / l1;
    const int r0 = q0 + warp * 16 + gid;
    const int r1 = r0 + 8;
#pragma unroll
    for (int ni = 0; ni < 8; ni++) {
        int cw = (ni * 8 + tg * 2) / 2;
        g_avw[(size_t)(bh * TSEQ + r0) * 32 + cw] =
            pack_bf16(oacc[ni][0] * il0, oacc[ni][1] * il0);
        g_avw[(size_t)(bh * TSEQ + r1) * 32 + cw] =
            pack_bf16(oacc[ni][2] * il1, oacc[ni][3] * il1);
    }
}

// ===========================================================================
// Kernel 3: O-projection + residual. Tile 64(m) x 128(n) -> grid 512 CTAs.
// 8 warps as 2(m) x 4(n); warp tile 32x32. ldmatrix frags.
// Smem words: A0@0 A1@2304 B0@4608 B1@9216  (55296 B total).
// A = av_perm (reference (H,B)-view quirk: chunk kt -> head h2 = kt).
// ===========================================================================
#define OP_SMEM_BYTES 55296

__global__ __launch_bounds__(256) void oproj_kernel(
    const float* __restrict__ inp)
{
    extern __shared__ __align__(16) uint32_t smw[];
    const uint32_t sb = smem_u32(smw);

    const int tid  = threadIdx.x;
    const int lane = tid & 31;
    const int warp = tid >> 5;
    const int gid  = lane >> 2;
    const int tg   = lane & 3;
    const int wm   = warp & 1;          // 2 m halves of 32
    const int wn   = warp >> 1;         // 4 n groups of 32
    const int mBase = blockIdx.y * 64;
    const int nBase = blockIdx.x * 128;

    const int lr  = lane & 15;
    const int lko = (lane >> 4) * 4;

    const char* gB = (const char*)g_wo_bf + (size_t)nBase * 2048;

    float acc[2][4][4];
#pragma unroll
    for (int mi = 0; mi < 2; mi++)
#pragma unroll
        for (int ni = 0; ni < 4; ni++)
#pragma unroll
            for (int j = 0; j < 4; j++) acc[mi][ni][j] = 0.f;

    auto issue = [&](int kt, int buf) {
        const uint32_t sa  = sb + (buf * 2304) * 4;
        const uint32_t sbb = sb + ((4608) + buf * 4608) * 4;
#pragma unroll
        for (int p = 0; p < 2; p++) {   // A: 64 rows x 8 = 512 copies
            int c = tid + p * 256;
            int row = c >> 3, col = c & 7;
            int m = mBase + row;
            int b2 = m >> 11, t = m & 2047;
            const char* ga = (const char*)g_avw +
                ((size_t)(kt * BATCH + b2) * TSEQ + t) * 128 + col * 16;
            cp16(sa + row * ROWB + col * 16, ga);
        }
#pragma unroll
        for (int p = 0; p < 4; p++) {   // B: 128 rows x 8 = 1024 copies
            int c = tid + p * 256;
            int row = c >> 3, col = c & 7;
            cp16(sbb + row * ROWB + col * 16,
                 gB + (size_t)row * 2048 + kt * 128 + col * 16);
        }
    };

    issue(0, 0);
    CP_COMMIT();

    for (int kt = 0; kt < 16; kt++) {
        const int buf = kt & 1;
        if (kt < 15) {
            issue(kt + 1, buf ^ 1);
            CP_COMMIT();
            CP_WAIT(1);
        } else {
            CP_WAIT(0);
        }
        __syncthreads();

        const uint32_t abase = sb + (buf * 2304) * 4;
        const uint32_t bbase = sb + (4608 + buf * 4608) * 4;
#pragma unroll
        for (int kk = 0; kk < 32; kk += 8) {
            uint32_t af[2][4];
#pragma unroll
            for (int mi = 0; mi < 2; mi++)
                ldm_x4(af[mi], abase +
                       ((wm * 32 + mi * 16 + lr) * GSTW + kk + lko) * 4);
#pragma unroll
            for (int p = 0; p < 2; p++) {
                uint32_t bf[4];
                ldm_x4(bf, bbase +
                       ((wn * 32 + p * 16 + lr) * GSTW + kk + lko) * 4);
                mma_bf16(acc[0][2 * p],     af[0], bf[0], bf[2]);
                mma_bf16(acc[0][2 * p + 1], af[0], bf[1], bf[3]);
                mma_bf16(acc[1][2 * p],     af[1], bf[0], bf[2]);
                mma_bf16(acc[1][2 * p + 1], af[1], bf[1], bf[3]);
            }
        }
        __syncthreads();
    }

    // epilogue: residual add (fp32), write g_y
#pragma unroll
    for (int mi = 0; mi < 2; mi++) {
        int r0 = mBase + wm * 32 + mi * 16 + gid;
        int r1 = r0 + 8;
#pragma unroll
        for (int ni = 0; ni < 4; ni++) {
            int n = nBase + wn * 32 + ni * 8 + tg * 2;
            float2 i0 = *(const float2*)(inp + (size_t)r0 * DMODEL + n);
            float2 i1 = *(const float2*)(inp + (size_t)r1 * DMODEL + n);
            *(float2*)(g_y + (size_t)r0 * DMODEL + n) =
                make_float2(acc[mi][ni][0] + i0.x, acc[mi][ni][1] + i0.y);
            *(float2*)(g_y + (size_t)r1 * DMODEL + n) =
                make_float2(acc[mi][ni][2] + i1.x, acc[mi][ni][3] + i1.y);
        }
    }
}

// ===========================================================================
// Kernel 4: LayerNorm. One warp per row of 1024.
// ===========================================================================
__global__ __launch_bounds__(256) void ln_kernel(
    const float* __restrict__ gamma,
    const float* __restrict__ beta,
    float* __restrict__ out)
{
    const int row  = blockIdx.x * 8 + (threadIdx.x >> 5);
    const int lane = threadIdx.x & 31;
    const float* x = g_y + (size_t)row * DMODEL;

    float4 v[8];
    float s1 = 0.f, s2 = 0.f;
#pragma unroll
    for (int i = 0; i < 8; i++) {
        v[i] = *(const float4*)(x + lane * 4 + i * 128);
        s1 += v[i].x + v[i].y + v[i].z + v[i].w;
        s2 += v[i].x * v[i].x + v[i].y * v[i].y + v[i].z * v[i].z + v[i].w * v[i].w;
    }
#pragma unroll
    for (int off = 16; off > 0; off >>= 1) {
        s1 += __shfl_xor_sync(0xFFFFFFFFu, s1, off);
        s2 += __shfl_xor_sync(0xFFFFFFFFu, s2, off);
    }
    float mu   = s1 * (1.0f / DMODEL);
    float var  = s2 * (1.0f / DMODEL) - mu * mu;
    float rstd = rsqrtf(var + LN_EPS);

    float* o = out + (size_t)row * DMODEL;
#pragma unroll
    for (int i = 0; i < 8; i++) {
        int cbase = lane * 4 + i * 128;
        float4 g = *(const float4*)(gamma + cbase);
        float4 b = *(const float4*)(beta + cbase);
        float4 r;
        r.x = (v[i].x - mu) * rstd * g.x + b.x;
        r.y = (v[i].y - mu) * rstd * g.y + b.y;
        r.z = (v[i].z - mu) * rstd * g.z + b.z;
        r.w = (v[i].w - mu) * rstd * g.w + b.w;
        *(float4*)(o + cbase) = r;
    }
}

// ===========================================================================
extern "C" void kernel_launch(void* const* d_in, const int* in_sizes, int n_in,
                              void* d_out, int out_size)
{
    const float* inp   = (const float*)d_in[0];
    const float* Wqkv  = (const float*)d_in[1];
    const float* bqkv  = (const float*)d_in[2];
    const float* Wo    = (const float*)d_in[3];
    const float* gamma = (const float*)d_in[4];
    const float* beta  = (const float*)d_in[5];
    float* out = (float*)d_out;

    cudaFuncSetAttribute(qkv_gemm_kernel,
                         cudaFuncAttributeMaxDynamicSharedMemorySize,
                         GEMM_SMEM_BYTES);
    cudaFuncSetAttribute(oproj_kernel,
                         cudaFuncAttributeMaxDynamicSharedMemorySize,
                         OP_SMEM_BYTES);
    cudaFuncSetAttribute(attn_kernel,
                         cudaFuncAttributeMaxDynamicSharedMemorySize,
                         ATTN_SMEM_BYTES);

    cvt_kernel<<<CVT_TOTAL / 256, 256>>>(inp, Wqkv, Wo);
    qkv_gemm_kernel<<<dim3(N_QKV / 128, MROWS / 128), 256, GEMM_SMEM_BYTES>>>(bqkv);
    attn_kernel<<<dim3(TSEQ / 128, BH), 256, ATTN_SMEM_BYTES>>>();
    oproj_kernel<<<dim3(DMODEL / 128, MROWS / 64), 256, OP_SMEM_BYTES>>>(inp);
    ln_kernel<<<MROWS / 8, 256>>>(gamma, beta, out);
}

// round 12
// speedup vs baseline: 6.5245x; 1.0388x over previous
#include <cuda_runtime.h>
#include <cuda_bf16.h>
#include <cstdint>

// Problem constants
#define BATCH   2
#define TSEQ    2048
#define NHEAD   16
#define DHEAD   64
#define DMODEL  1024
#define BH      (BATCH * NHEAD)        // 32
#define MROWS   (BATCH * TSEQ)         // 4096
#define N_QKV   (3 * NHEAD * DHEAD)    // 3072
#define ATTN_SCALE 0.125f              // 1/sqrt(64)
#define LN_EPS  1e-5f

// ---------------- scratch (static device globals; no allocations) ----------
__device__ __align__(16) uint32_t g_inp_bf [MROWS * DMODEL / 2];
__device__ __align__(16) uint32_t g_wqkv_bf[N_QKV * DMODEL / 2];
__device__ __align__(16) uint32_t g_wo_bf  [DMODEL * DMODEL / 2];
__device__ __align__(16) uint32_t g_qw [BH * TSEQ * 32];  // [bh][t][d/2]
__device__ __align__(16) uint32_t g_kw [BH * TSEQ * 32];
__device__ __align__(16) uint32_t g_vw [BH * TSEQ * 32];
__device__ __align__(16) uint32_t g_avw[BH * TSEQ * 32];  // attn out, L=b*16+h
__device__ float g_y[MROWS * DMODEL];                     // pre-LN fp32

// ---------------- helpers --------------------------------------------------
__device__ __forceinline__ uint32_t pack_bf16(float lo, float hi) {
    __nv_bfloat162 h = __floats2bfloat162_rn(lo, hi);
    return *reinterpret_cast<uint32_t*>(&h);
}

__device__ __forceinline__ uint32_t smem_u32(const void* p) {
    uint32_t a;
    asm("{ .reg .u64 t; cvta.to.shared.u64 t, %1; cvt.u32.u64 %0, t; }"
        : "=r"(a) : "l"(p));
    return a;
}

__device__ __forceinline__ void cp16(uint32_t s, const void* g) {
    asm volatile("cp.async.cg.shared.global [%0], [%1], 16;"
                 :: "r"(s), "l"(g) : "memory");
}
#define CP_COMMIT() asm volatile("cp.async.commit_group;" ::: "memory")
#define CP_WAIT(n)  asm volatile("cp.async.wait_group %0;" :: "n"(n) : "memory")

__device__ __forceinline__ void ldm_x4(uint32_t* r, uint32_t a) {
    asm volatile("ldmatrix.sync.aligned.m8n8.x4.shared.b16 {%0,%1,%2,%3}, [%4];"
                 : "=r"(r[0]), "=r"(r[1]), "=r"(r[2]), "=r"(r[3]) : "r"(a));
}
__device__ __forceinline__ void ldm_x4_t(uint32_t* r, uint32_t a) {
    asm volatile("ldmatrix.sync.aligned.m8n8.x4.trans.shared.b16 {%0,%1,%2,%3}, [%4];"
                 : "=r"(r[0]), "=r"(r[1]), "=r"(r[2]), "=r"(r[3]) : "r"(a));
}

// mma.sync m16n8k16 bf16 (fp32 accum).
__device__ __forceinline__ void mma_bf16(float* c, const uint32_t* a,
                                         uint32_t b0, uint32_t b1) {
    asm volatile(
        "mma.sync.aligned.m16n8k16.row.col.f32.bf16.bf16.f32 "
        "{%0,%1,%2,%3}, {%4,%5,%6,%7}, {%8,%9}, {%0,%1,%2,%3};"
        : "+f"(c[0]), "+f"(c[1]), "+f"(c[2]), "+f"(c[3])
        : "r"(a[0]), "r"(a[1]), "r"(a[2]), "r"(a[3]), "r"(b0), "r"(b1));
}

#define GSTW 36           // smem row stride in words (4 mod 32 -> conflict-free)
#define ROWB (GSTW * 4)   // 144 bytes

// ===========================================================================
// Kernel 0: one-time fp32 -> bf16 pre-convert of inp / W_qkv / W_o.
// ===========================================================================
#define CVT_T1 (MROWS * DMODEL / 4)
#define CVT_T2 (N_QKV * DMODEL / 4)
#define CVT_T3 (DMODEL * DMODEL / 4)
#define CVT_TOTAL (CVT_T1 + CVT_T2 + CVT_T3)

__global__ __launch_bounds__(256) void cvt_kernel(
    const float* __restrict__ inp,
    const float* __restrict__ wqkv,
    const float* __restrict__ wo)
{
    int idx = blockIdx.x * 256 + threadIdx.x;
    const float4* src;
    uint2* dst;
    int li;
    if (idx < CVT_T1) {
        src = (const float4*)inp;  dst = (uint2*)g_inp_bf;  li = idx;
    } else if (idx < CVT_T1 + CVT_T2) {
        src = (const float4*)wqkv; dst = (uint2*)g_wqkv_bf; li = idx - CVT_T1;
    } else {
        src = (const float4*)wo;   dst = (uint2*)g_wo_bf;   li = idx - CVT_T1 - CVT_T2;
    }
    float4 v = src[li];
    dst[li] = make_uint2(pack_bf16(v.x, v.y), pack_bf16(v.z, v.w));
}

// ===========================================================================
// Projection GEMMs: block 128x128, 8 warps (4m x 2n), warp tile 32x64,
// k-chunk 64 bf16, THREE-stage cp.async pipeline (ONE sync per chunk).
// Smem words: A stages @ s*4608, B stages @ 13824 + s*4608. 110592 B total.
// ===========================================================================
#define NSTAGE 3
#define GEMM_SMEM_BYTES (6 * 4608 * 4)   // 110592

// ---- Kernel 1: QKV ----
__device__ __forceinline__ void qkv_issue(
    uint32_t sbase, const char* gA, const char* gB, int kt, int stg, int tid)
{
    const uint32_t sa  = sbase + stg * 4608 * 4;
    const uint32_t sbb = sbase + (13824 + stg * 4608) * 4;
#pragma unroll
    for (int p = 0; p < 4; p++) {
        int c = tid + p * 256;
        int row = c >> 3, col = c & 7;
        cp16(sa  + row * ROWB + col * 16, gA + (size_t)row * 2048 + kt * 128 + col * 16);
        cp16(sbb + row * ROWB + col * 16, gB + (size_t)row * 2048 + kt * 128 + col * 16);
    }
}

__global__ __launch_bounds__(256) void qkv_gemm_kernel(
    const float* __restrict__ bias)
{
    extern __shared__ __align__(16) uint32_t smw[];
    const uint32_t sb = smem_u32(smw);

    const int tid  = threadIdx.x;
    const int lane = tid & 31;
    const int warp = tid >> 5;
    const int gid  = lane >> 2;
    const int tg   = lane & 3;
    const int wm   = warp & 3;
    const int wn   = warp >> 2;
    const int mBase = blockIdx.y * 128;
    const int nBase = blockIdx.x * 128;

    const int lr  = lane & 15;
    const int lko = (lane >> 4) * 4;

    const char* gA = (const char*)g_inp_bf  + (size_t)mBase * 2048;
    const char* gB = (const char*)g_wqkv_bf + (size_t)nBase * 2048;

    float acc[2][8][4];
#pragma unroll
    for (int mi = 0; mi < 2; mi++)
#pragma unroll
        for (int ni = 0; ni < 8; ni++)
#pragma unroll
            for (int j = 0; j < 4; j++) acc[mi][ni][j] = 0.f;

    qkv_issue(sb, gA, gB, 0, 0, tid); CP_COMMIT();
    qkv_issue(sb, gA, gB, 1, 1, tid); CP_COMMIT();

    for (int kt = 0; kt < 16; kt++) {
        const int stg = kt % NSTAGE;
        CP_WAIT(1);
        __syncthreads();

        const uint32_t abase = sb + (stg * 4608) * 4;
        const uint32_t bbase = sb + ((13824 + stg * 4608)) * 4;
#pragma unroll
        for (int kk = 0; kk < 32; kk += 8) {
            uint32_t af[2][4];
#pragma unroll
            for (int mi = 0; mi < 2; mi++)
                ldm_x4(af[mi], abase +
                       ((wm * 32 + mi * 16 + lr) * GSTW + kk + lko) * 4);
#pragma unroll
            for (int p = 0; p < 4; p++) {
                uint32_t bf[4];
                ldm_x4(bf, bbase +
                       ((wn * 64 + p * 16 + lr) * GSTW + kk + lko) * 4);
                mma_bf16(acc[0][2 * p],     af[0], bf[0], bf[2]);
                mma_bf16(acc[0][2 * p + 1], af[0], bf[1], bf[3]);
                mma_bf16(acc[1][2 * p],     af[1], bf[0], bf[2]);
                mma_bf16(acc[1][2 * p + 1], af[1], bf[1], bf[3]);
            }
        }
        // issue stage kt+2 (buffer consumed at kt-1; safe after this sync)
        if (kt + 2 < 16)
            qkv_issue(sb, gA, gB, kt + 2, (kt + 2) % NSTAGE, tid);
        CP_COMMIT();   // uniform group count (empty groups at tail)
    }

#pragma unroll
    for (int mi = 0; mi < 2; mi++) {
        int r0 = mBase + wm * 32 + mi * 16 + gid;
        int r1 = r0 + 8;
        int bb0 = r0 >> 11, t0 = r0 & 2047;
        int bb1 = r1 >> 11, t1 = r1 & 2047;
#pragma unroll
        for (int ni = 0; ni < 8; ni++) {
            int n = nBase + wn * 64 + ni * 8 + tg * 2;
            int third = n >> 10;
            int nn = n & 1023;
            int h = nn >> 6, d = nn & 63;
            uint32_t* base = (third == 0) ? g_qw : ((third == 1) ? g_kw : g_vw);
            float2 bi = *(const float2*)(bias + n);
            base[((bb0 * NHEAD + h) * TSEQ + t0) * 32 + d / 2] =
                pack_bf16(acc[mi][ni][0] + bi.x, acc[mi][ni][1] + bi.y);
            base[((bb1 * NHEAD + h) * TSEQ + t1) * 32 + d / 2] =
                pack_bf16(acc[mi][ni][2] + bi.x, acc[mi][ni][3] + bi.y);
        }
    }
}

// ===========================================================================
// Kernel 2: flash attention, register softmax + ldmatrix frags (as R10).
// ===========================================================================
#define QB_OFF  0
#define KB_OFF  (128 * GSTW)                     // 4608
#define VS_OFF  (KB_OFF + 2 * 64 * GSTW)         // 9216
#define ATTN_SMEM_WORDS (VS_OFF + 2 * 64 * GSTW) // 13824
#define ATTN_SMEM_BYTES (ATTN_SMEM_WORDS * 4)    // 55296

__global__ __launch_bounds__(256) void attn_kernel()
{
    extern __shared__ __align__(16) uint32_t smw[];
    const uint32_t sb = smem_u32(smw);

    const int tid  = threadIdx.x;
    const int lane = tid & 31;
    const int warp = tid >> 5;
    const int gid  = lane >> 2;
    const int tg   = lane & 3;
    const int bh   = blockIdx.y;
    const int q0   = blockIdx.x * 128;

    const int lr  = lane & 15;
    const int lko = (lane >> 4) * 4;

    auto kv_issue = [&](int kt, int buf) {
        const char* gk = (const char*)g_kw + (size_t)(bh * TSEQ + kt * 64) * 128;
        const char* gv = (const char*)g_vw + (size_t)(bh * TSEQ + kt * 64) * 128;
        const uint32_t kbb = sb + (KB_OFF + buf * 64 * GSTW) * 4;
        const uint32_t vbb = sb + (VS_OFF + buf * 64 * GSTW) * 4;
#pragma unroll
        for (int p = 0; p < 2; p++) {
            int c = tid + p * 256;
            int row = c >> 3, col = c & 7;
            cp16(kbb + row * ROWB + col * 16, gk + row * 128 + col * 16);
            cp16(vbb + row * ROWB + col * 16, gv + row * 128 + col * 16);
        }
    };

    kv_issue(0, 0);
    CP_COMMIT();
    {
        const int qr = tid >> 1;
        const int hb = (tid & 1) * 16;
        const uint32_t* gq = g_qw + (size_t)(bh * TSEQ + q0 + qr) * 32 + hb;
        uint32_t* qrow = &smw[QB_OFF + qr * GSTW + hb];
#pragma unroll
        for (int i = 0; i < 4; i++)
            *(uint4*)&qrow[i * 4] = *(const uint4*)(gq + i * 4);
    }
    CP_WAIT(0);
    __syncthreads();

    uint32_t qf[4][4];
#pragma unroll
    for (int j = 0; j < 4; j++)
        ldm_x4(qf[j], sb + (QB_OFF + (warp * 16 + lr) * GSTW + j * 8 + lko) * 4);

    float oacc[8][4];
#pragma unroll
    for (int ni = 0; ni < 8; ni++)
#pragma unroll
        for (int j = 0; j < 4; j++) oacc[ni][j] = 0.f;
    float m0 = -1e30f, m1 = -1e30f, l0 = 0.f, l1 = 0.f;

    for (int kt = 0; kt < TSEQ / 64; kt++) {
        const int buf = kt & 1;
        if (kt < TSEQ / 64 - 1) {
            kv_issue(kt + 1, buf ^ 1);
            CP_COMMIT();
        }

        float s[8][4];
#pragma unroll
        for (int ni = 0; ni < 8; ni++)
#pragma unroll
            for (int j = 0; j < 4; j++) s[ni][j] = 0.f;
        const uint32_t kbase = sb + (KB_OFF + buf * 64 * GSTW) * 4;
#pragma unroll
        for (int j = 0; j < 4; j++) {
#pragma unroll
            for (int p = 0; p < 4; p++) {
                uint32_t bf[4];
                ldm_x4(bf, kbase + ((p * 16 + lr) * GSTW + j * 8 + lko) * 4);
                mma_bf16(s[2 * p],     qf[j], bf[0], bf[2]);
                mma_bf16(s[2 * p + 1], qf[j], bf[1], bf[3]);
            }
        }

        float mx0 = -1e30f, mx1 = -1e30f;
#pragma unroll
        for (int ni = 0; ni < 8; ni++) {
            s[ni][0] *= ATTN_SCALE; s[ni][1] *= ATTN_SCALE;
            s[ni][2] *= ATTN_SCALE; s[ni][3] *= ATTN_SCALE;
            mx0 = fmaxf(mx0, fmaxf(s[ni][0], s[ni][1]));
            mx1 = fmaxf(mx1, fmaxf(s[ni][2], s[ni][3]));
        }
        mx0 = fmaxf(mx0, __shfl_xor_sync(0xFFFFFFFFu, mx0, 1));
        mx0 = fmaxf(mx0, __shfl_xor_sync(0xFFFFFFFFu, mx0, 2));
        mx1 = fmaxf(mx1, __shfl_xor_sync(0xFFFFFFFFu, mx1, 1));
        mx1 = fmaxf(mx1, __shfl_xor_sync(0xFFFFFFFFu, mx1, 2));
        const float nm0 = fmaxf(m0, mx0), nm1 = fmaxf(m1, mx1);
        const float cr0 = __expf(m0 - nm0), cr1 = __expf(m1 - nm1);
        m0 = nm0; m1 = nm1;

        float sum0 = 0.f, sum1 = 0.f;
#pragma unroll
        for (int ni = 0; ni < 8; ni++) {
            s[ni][0] = __expf(s[ni][0] - nm0);
            s[ni][1] = __expf(s[ni][1] - nm0);
            s[ni][2] = __expf(s[ni][2] - nm1);
            s[ni][3] = __expf(s[ni][3] - nm1);
            sum0 += s[ni][0] + s[ni][1];
            sum1 += s[ni][2] + s[ni][3];
        }
        sum0 += __shfl_xor_sync(0xFFFFFFFFu, sum0, 1);
        sum0 += __shfl_xor_sync(0xFFFFFFFFu, sum0, 2);
        sum1 += __shfl_xor_sync(0xFFFFFFFFu, sum1, 1);
        sum1 += __shfl_xor_sync(0xFFFFFFFFu, sum1, 2);
        l0 = l0 * cr0 + sum0;
        l1 = l1 * cr1 + sum1;

        uint32_t pf[4][4];
#pragma unroll
        for (int j = 0; j < 4; j++) {
            pf[j][0] = pack_bf16(s[2 * j][0],     s[2 * j][1]);
            pf[j][1] = pack_bf16(s[2 * j][2],     s[2 * j][3]);
            pf[j][2] = pack_bf16(s[2 * j + 1][0], s[2 * j + 1][1]);
            pf[j][3] = pack_bf16(s[2 * j + 1][2], s[2 * j + 1][3]);
        }

#pragma unroll
        for (int ni = 0; ni < 8; ni++) {
            oacc[ni][0] *= cr0; oacc[ni][1] *= cr0;
            oacc[ni][2] *= cr1; oacc[ni][3] *= cr1;
        }

        const uint32_t vbase = sb + (VS_OFF + buf * 64 * GSTW) * 4;
#pragma unroll
        for (int j = 0; j < 4; j++) {
#pragma unroll
            for (int p = 0; p < 4; p++) {
                uint32_t vf[4];
                ldm_x4_t(vf, vbase + (j * 16 + lr) * ROWB + p * 32 + (lane >> 4) * 16);
                mma_bf16(oacc[2 * p],     pf[j], vf[0], vf[1]);
                mma_bf16(oacc[2 * p + 1], pf[j], vf[2], vf[3]);
            }
        }

        if (kt < TSEQ / 64 - 1) CP_WAIT(0);
        __syncthreads();
    }

    const float il0 = 1.0f / l0, il1 = 1.0f / l1;
    const int r0 = q0 + warp * 16 + gid;
    const int r1 = r0 + 8;
#pragma unroll
    for (int ni = 0; ni < 8; ni++) {
        int cw = (ni * 8 + tg * 2) / 2;
        g_avw[(size_t)(bh * TSEQ + r0) * 32 + cw] =
            pack_bf16(oacc[ni][0] * il0, oacc[ni][1] * il0);
        g_avw[(size_t)(bh * TSEQ + r1) * 32 + cw] =
            pack_bf16(oacc[ni][2] * il1, oacc[ni][3] * il1);
    }
}

// ===========================================================================
// Kernel 3: O-projection + residual, 128x128 tile, 3-stage pipeline.
// A = av_perm (reference (H,B)-view quirk: chunk kt -> head h2 = kt).
// ===========================================================================
__global__ __launch_bounds__(256) void oproj_kernel(
    const float* __restrict__ inp)
{
    extern __shared__ __align__(16) uint32_t smw[];
    const uint32_t sb = smem_u32(smw);

    const int tid  = threadIdx.x;
    const int lane = tid & 31;
    const int warp = tid >> 5;
    const int gid  = lane >> 2;
    const int tg   = lane & 3;
    const int wm   = warp & 3;
    const int wn   = warp >> 2;
    const int mBase = blockIdx.y * 128;
    const int nBase = blockIdx.x * 128;

    const int lr  = lane & 15;
    const int lko = (lane >> 4) * 4;

    const char* gB = (const char*)g_wo_bf + (size_t)nBase * 2048;

    float acc[2][8][4];
#pragma unroll
    for (int mi = 0; mi < 2; mi++)
#pragma unroll
        for (int ni = 0; ni < 8; ni++)
#pragma unroll
            for (int j = 0; j < 4; j++) acc[mi][ni][j] = 0.f;

    auto issue = [&](int kt, int stg) {
        const uint32_t sa  = sb + stg * 4608 * 4;
        const uint32_t sbb = sb + (13824 + stg * 4608) * 4;
#pragma unroll
        for (int p = 0; p < 4; p++) {
            int c = tid + p * 256;
            int row = c >> 3, col = c & 7;
            int m = mBase + row;
            int b2 = m >> 11, t = m & 2047;
            const char* ga = (const char*)g_avw +
                ((size_t)(kt * BATCH + b2) * TSEQ + t) * 128 + col * 16;
            cp16(sa + row * ROWB + col * 16, ga);
            cp16(sbb + row * ROWB + col * 16,
                 gB + (size_t)row * 2048 + kt * 128 + col * 16);
        }
    };

    issue(0, 0); CP_COMMIT();
    issue(1, 1); CP_COMMIT();

    for (int kt = 0; kt < 16; kt++) {
        const int stg = kt % NSTAGE;
        CP_WAIT(1);
        __syncthreads();

        const uint32_t abase = sb + (stg * 4608) * 4;
        const uint32_t bbase = sb + (13824 + stg * 4608) * 4;
#pragma unroll
        for (int kk = 0; kk < 32; kk += 8) {
            uint32_t af[2][4];
#pragma unroll
            for (int mi = 0; mi < 2; mi++)
                ldm_x4(af[mi], abase +
                       ((wm * 32 + mi * 16 + lr) * GSTW + kk + lko) * 4);
#pragma unroll
            for (int p = 0; p < 4; p++) {
                uint32_t bf[4];
                ldm_x4(bf, bbase +
                       ((wn * 64 + p * 16 + lr) * GSTW + kk + lko) * 4);
                mma_bf16(acc[0][2 * p],     af[0], bf[0], bf[2]);
                mma_bf16(acc[0][2 * p + 1], af[0], bf[1], bf[3]);
                mma_bf16(acc[1][2 * p],     af[1], bf[0], bf[2]);
                mma_bf16(acc[1][2 * p + 1], af[1], bf[1], bf[3]);
            }
        }
        if (kt + 2 < 16)
            issue(kt + 2, (kt + 2) % NSTAGE);
        CP_COMMIT();
    }

#pragma unroll
    for (int mi = 0; mi < 2; mi++) {
        int r0 = mBase + wm * 32 + mi * 16 + gid;
        int r1 = r0 + 8;
#pragma unroll
        for (int ni = 0; ni < 8; ni++) {
            int n = nBase + wn * 64 + ni * 8 + tg * 2;
            float2 i0 = *(const float2*)(inp + (size_t)r0 * DMODEL + n);
            float2 i1 = *(const float2*)(inp + (size_t)r1 * DMODEL + n);
            *(float2*)(g_y + (size_t)r0 * DMODEL + n) =
                make_float2(acc[mi][ni][0] + i0.x, acc[mi][ni][1] + i0.y);
            *(float2*)(g_y + (size_t)r1 * DMODEL + n) =
                make_float2(acc[mi][ni][2] + i1.x, acc[mi][ni][3] + i1.y);
        }
    }
}

// ===========================================================================
// Kernel 4: LayerNorm. One warp per row of 1024.
// ===========================================================================
__global__ __launch_bounds__(256) void ln_kernel(
    const float* __restrict__ gamma,
    const float* __restrict__ beta,
    float* __restrict__ out)
{
    const int row  = blockIdx.x * 8 + (threadIdx.x >> 5);
    const int lane = threadIdx.x & 31;
    const float* x = g_y + (size_t)row * DMODEL;

    float4 v[8];
    float s1 = 0.f, s2 = 0.f;
#pragma unroll
    for (int i = 0; i < 8; i++) {
        v[i] = *(const float4*)(x + lane * 4 + i * 128);
        s1 += v[i].x + v[i].y + v[i].z + v[i].w;
        s2 += v[i].x * v[i].x + v[i].y * v[i].y + v[i].z * v[i].z + v[i].w * v[i].w;
    }
#pragma unroll
    for (int off = 16; off > 0; off >>= 1) {
        s1 += __shfl_xor_sync(0xFFFFFFFFu, s1, off);
        s2 += __shfl_xor_sync(0xFFFFFFFFu, s2, off);
    }
    float mu   = s1 * (1.0f / DMODEL);
    float var  = s2 * (1.0f / DMODEL) - mu * mu;
    float rstd = rsqrtf(var + LN_EPS);

    float* o = out + (size_t)row * DMODEL;
#pragma unroll
    for (int i = 0; i < 8; i++) {
        int cbase = lane * 4 + i * 128;
        float4 g = *(const float4*)(gamma + cbase);
        float4 b = *(const float4*)(beta + cbase);
        float4 r;
        r.x = (v[i].x - mu) * rstd * g.x + b.x;
        r.y = (v[i].y - mu) * rstd * g.y + b.y;
        r.z = (v[i].z - mu) * rstd * g.z + b.z;
        r.w = (v[i].w - mu) * rstd * g.w + b.w;
        *(float4*)(o + cbase) = r;
    }
}

// ===========================================================================
extern "C" void kernel_launch(void* const* d_in, const int* in_sizes, int n_in,
                              void* d_out, int out_size)
{
    const float* inp   = (const float*)d_in[0];
    const float* Wqkv  = (const float*)d_in[1];
    const float* bqkv  = (const float*)d_in[2];
    const float* Wo    = (const float*)d_in[3];
    const float* gamma = (const float*)d_in[4];
    const float* beta  = (const float*)d_in[5];
    float* out = (float*)d_out;

    cudaFuncSetAttribute(qkv_gemm_kernel,
                         cudaFuncAttributeMaxDynamicSharedMemorySize,
                         GEMM_SMEM_BYTES);
    cudaFuncSetAttribute(oproj_kernel,
                         cudaFuncAttributeMaxDynamicSharedMemorySize,
                         GEMM_SMEM_BYTES);
    cudaFuncSetAttribute(attn_kernel,
                         cudaFuncAttributeMaxDynamicSharedMemorySize,
                         ATTN_SMEM_BYTES);

    cvt_kernel<<<CVT_TOTAL / 256, 256>>>(inp, Wqkv, Wo);
    qkv_gemm_kernel<<<dim3(N_QKV / 128, MROWS / 128), 256, GEMM_SMEM_BYTES>>>(bqkv);
    attn_kernel<<<dim3(TSEQ / 128, BH), 256, ATTN_SMEM_BYTES>>>();
    oproj_kernel<<<dim3(DMODEL / 128, MROWS / 128), 256, GEMM_SMEM_BYTES>>>(inp);
    ln_kernel<<<MROWS / 8, 256>>>(gamma, beta, out);
}